// round 1
// baseline (speedup 1.0000x reference)
#include <cuda_runtime.h>
#include <cuda_bf16.h>
#include <math.h>

// Problem constants
#define BATCH 8
#define LSEQ 1024
#define DMODEL 1024
#define NHEAD 16
#define HDIM 64
#define DFF 4096
#define MROWS (BATCH * LSEQ)   // 8192
#define ATT_SCALE 0.125f       // 64^-0.5
#define LN_EPS 1e-5f

// ---------------- scratch (device globals; no allocation allowed) ----------
__device__ float g_qp[MROWS * DMODEL];
__device__ float g_kp[MROWS * DMODEL];
__device__ float g_vp[MROWS * DMODEL];
__device__ float g_att[MROWS * DMODEL];
__device__ float g_y[MROWS * DMODEL];
__device__ float g_x[MROWS * DMODEL];
__device__ float g_h[(size_t)MROWS * DFF];
__device__ int g_allpad[BATCH];
__device__ unsigned char g_emask[BATCH * LSEQ];
__device__ int g_mstride[1];

// ---------------- SGEMM: C = A[M,K] @ B[K,N] + bias (+relu) (+res) --------
// 128x128 block tile, BK=8, 256 threads, 8x8 per thread.
__global__ __launch_bounds__(256, 2) void sgemm_kernel(
    const float* __restrict__ A, const float* __restrict__ B,
    const float* __restrict__ bias, const float* __restrict__ res,
    float* __restrict__ C, int M, int N, int K, int doRelu) {
    __shared__ __align__(16) float As[8][128];
    __shared__ __align__(16) float Bs[8][128];
    const int tid = threadIdx.x;
    const int bcol = blockIdx.x, brow = blockIdx.y;
    const int tx = tid & 15, ty = tid >> 4;
    const int aRow = tid >> 1, aCol = (tid & 1) * 4;
    const int bRow = tid >> 5, bCol = (tid & 31) * 4;
    const float* Ag = A + (size_t)brow * 128 * K;
    const float* Bg = B + (size_t)bcol * 128;
    float acc[8][8] = {};
    for (int k0 = 0; k0 < K; k0 += 8) {
        float4 av = *(const float4*)(Ag + (size_t)aRow * K + k0 + aCol);
        As[aCol + 0][aRow] = av.x;
        As[aCol + 1][aRow] = av.y;
        As[aCol + 2][aRow] = av.z;
        As[aCol + 3][aRow] = av.w;
        float4 bv = *(const float4*)(Bg + (size_t)(k0 + bRow) * N + bCol);
        *(float4*)&Bs[bRow][bCol] = bv;
        __syncthreads();
#pragma unroll
        for (int k = 0; k < 8; k++) {
            float4 a0 = *(const float4*)&As[k][ty * 8];
            float4 a1 = *(const float4*)&As[k][ty * 8 + 4];
            float4 b0 = *(const float4*)&Bs[k][tx * 8];
            float4 b1 = *(const float4*)&Bs[k][tx * 8 + 4];
            float ra[8] = {a0.x, a0.y, a0.z, a0.w, a1.x, a1.y, a1.z, a1.w};
            float rb[8] = {b0.x, b0.y, b0.z, b0.w, b1.x, b1.y, b1.z, b1.w};
#pragma unroll
            for (int i = 0; i < 8; i++)
#pragma unroll
                for (int j = 0; j < 8; j++)
                    acc[i][j] = fmaf(ra[i], rb[j], acc[i][j]);
        }
        __syncthreads();
    }
#pragma unroll
    for (int i = 0; i < 8; i++) {
        int row = brow * 128 + ty * 8 + i;
#pragma unroll
        for (int jv = 0; jv < 2; jv++) {
            int col = bcol * 128 + tx * 8 + jv * 4;
            float4 bb = *(const float4*)(bias + col);
            float4 o;
            o.x = acc[i][jv * 4 + 0] + bb.x;
            o.y = acc[i][jv * 4 + 1] + bb.y;
            o.z = acc[i][jv * 4 + 2] + bb.z;
            o.w = acc[i][jv * 4 + 3] + bb.w;
            if (doRelu) {
                o.x = fmaxf(o.x, 0.f); o.y = fmaxf(o.y, 0.f);
                o.z = fmaxf(o.z, 0.f); o.w = fmaxf(o.w, 0.f);
            }
            if (res) {
                float4 rv = *(const float4*)(res + (size_t)row * N + col);
                o.x += rv.x; o.y += rv.y; o.z += rv.z; o.w += rv.w;
            }
            *(float4*)(C + (size_t)row * N + col) = o;
        }
    }
}

// ---------------- mask dtype detection + normalization ---------------------
// numpy bool -> 1 byte; some pipelines widen bool to int32 (LE). If every byte
// at offset (4j+1) is zero we conclude int32 layout (prob 2^-4096 false pos).
__global__ void detect_mask_stride(const unsigned char* __restrict__ m, int* stride_out) {
    __shared__ int any;
    if (threadIdx.x == 0) any = 0;
    __syncthreads();
    int a = 0;
    for (int j = threadIdx.x; j < 2048; j += 256) a |= m[j * 4 + 1];
    if (a) atomicOr(&any, 1);
    __syncthreads();
    if (threadIdx.x == 0) *stride_out = any ? 1 : 4;
}

__global__ void mask_prep(const unsigned char* __restrict__ m,
                          const int* __restrict__ stridep,
                          unsigned char* __restrict__ em, int* __restrict__ allpad) {
    int b = blockIdx.x;
    int st = *stridep;
    int ok = 1;
    for (int j = threadIdx.x; j < LSEQ; j += 256) {
        unsigned char v = (m[(size_t)(b * LSEQ + j) * st] != 0) ? 1 : 0;
        em[b * LSEQ + j] = v;
        ok &= (int)v;
    }
    ok = __syncthreads_and(ok);
    if (threadIdx.x == 0) allpad[b] = ok;
}

// ---------------- flash-style attention ------------------------------------
// grid (Lq/64, H, B), 256 threads. Tiles: Q 64x64, stream K/V in 64-key tiles.
// Qst/Kst stored d-major (stride 68) so S-GEMM inner loop is 2x LDS.128 / 16 FMA.
#define ATT_SMEM_FLOATS (4 * 64 * 68 + 4 * 64)
#define ATT_SMEM_BYTES (ATT_SMEM_FLOATS * 4)

__global__ __launch_bounds__(256) void attn_kernel(
    const float* __restrict__ qp, const float* __restrict__ kp,
    const float* __restrict__ vp, const unsigned char* __restrict__ em,
    const int* __restrict__ allpad, float* __restrict__ out) {
    extern __shared__ float sm[];
    float* Qst = sm;                    // [d][i], stride 68
    float* Kst = sm + 64 * 68;          // [d][j]
    float* Vs  = sm + 2 * 64 * 68;      // [k][c]
    float* Ps  = sm + 3 * 64 * 68;      // [i][k]
    float* rowm = sm + 4 * 64 * 68;
    float* rowl = rowm + 64;
    float* rowa = rowl + 64;
    float* mk   = rowa + 64;

    const int b = blockIdx.z, h = blockIdx.y, q0 = blockIdx.x * 64;
    const int tid = threadIdx.x;
    const int tx = tid & 15, ty = tid >> 4;
    const int i0 = ty * 4, j0 = tx * 4;
    const int ap = allpad[b];
    const size_t qoff = ((size_t)(b * LSEQ + q0) * DMODEL) + h * HDIM;

    for (int t = tid; t < 64 * 16; t += 256) {
        int i = t >> 4, c4 = (t & 15) * 4;
        float4 v = *(const float4*)(qp + qoff + (size_t)i * DMODEL + c4);
        Qst[(c4 + 0) * 68 + i] = v.x;
        Qst[(c4 + 1) * 68 + i] = v.y;
        Qst[(c4 + 2) * 68 + i] = v.z;
        Qst[(c4 + 3) * 68 + i] = v.w;
    }
    if (tid < 64) { rowm[tid] = -1e30f; rowl[tid] = 0.f; }
    float acc[4][4] = {};

    for (int kt = 0; kt < 16; kt++) {
        const size_t koff = ((size_t)(b * LSEQ + kt * 64) * DMODEL) + h * HDIM;
        for (int t = tid; t < 64 * 16; t += 256) {
            int j = t >> 4, c4 = (t & 15) * 4;
            float4 kvv = *(const float4*)(kp + koff + (size_t)j * DMODEL + c4);
            Kst[(c4 + 0) * 68 + j] = kvv.x;
            Kst[(c4 + 1) * 68 + j] = kvv.y;
            Kst[(c4 + 2) * 68 + j] = kvv.z;
            Kst[(c4 + 3) * 68 + j] = kvv.w;
            float4 vvv = *(const float4*)(vp + koff + (size_t)j * DMODEL + c4);
            *(float4*)&Vs[j * 68 + c4] = vvv;
        }
        if (tid < 64) {
            int kidx = kt * 64 + tid;
            int msk = em[b * LSEQ + kidx];
            if (ap && kidx == LSEQ - 1) msk = 0;
            mk[tid] = msk ? 1.0f : 0.0f;
        }
        __syncthreads();

        // S = Q K^T
        float s[4][4] = {};
#pragma unroll 8
        for (int d = 0; d < 64; d++) {
            float4 qv = *(const float4*)&Qst[d * 68 + i0];
            float4 kvv = *(const float4*)&Kst[d * 68 + j0];
            float qa[4] = {qv.x, qv.y, qv.z, qv.w};
            float kb[4] = {kvv.x, kvv.y, kvv.z, kvv.w};
#pragma unroll
            for (int ii = 0; ii < 4; ii++)
#pragma unroll
                for (int jj = 0; jj < 4; jj++)
                    s[ii][jj] = fmaf(qa[ii], kb[jj], s[ii][jj]);
        }
        // scale + mask, write to Ps
#pragma unroll
        for (int ii = 0; ii < 4; ii++) {
            float4 o;
            float* pp = (float*)&o;
#pragma unroll
            for (int jj = 0; jj < 4; jj++) {
                float v = s[ii][jj] * ATT_SCALE;
                pp[jj] = (mk[j0 + jj] != 0.f) ? -10000.0f : v;
            }
            *(float4*)&Ps[(i0 + ii) * 68 + j0] = o;
        }
        __syncthreads();

        // online softmax: 4 threads per row
        {
            int row = tid >> 2, sub = tid & 3;
            int base = row * 68 + sub * 16;
            float4 p0 = *(float4*)&Ps[base];
            float4 p1 = *(float4*)&Ps[base + 4];
            float4 p2 = *(float4*)&Ps[base + 8];
            float4 p3 = *(float4*)&Ps[base + 12];
            float tm = fmaxf(fmaxf(fmaxf(p0.x, p0.y), fmaxf(p0.z, p0.w)),
                             fmaxf(fmaxf(p1.x, p1.y), fmaxf(p1.z, p1.w)));
            tm = fmaxf(tm, fmaxf(fmaxf(fmaxf(p2.x, p2.y), fmaxf(p2.z, p2.w)),
                                 fmaxf(fmaxf(p3.x, p3.y), fmaxf(p3.z, p3.w))));
            tm = fmaxf(tm, __shfl_xor_sync(0xffffffffu, tm, 1));
            tm = fmaxf(tm, __shfl_xor_sync(0xffffffffu, tm, 2));
            float m_old = rowm[row];
            float newm = fmaxf(m_old, tm);
            p0.x = __expf(p0.x - newm); p0.y = __expf(p0.y - newm);
            p0.z = __expf(p0.z - newm); p0.w = __expf(p0.w - newm);
            p1.x = __expf(p1.x - newm); p1.y = __expf(p1.y - newm);
            p1.z = __expf(p1.z - newm); p1.w = __expf(p1.w - newm);
            p2.x = __expf(p2.x - newm); p2.y = __expf(p2.y - newm);
            p2.z = __expf(p2.z - newm); p2.w = __expf(p2.w - newm);
            p3.x = __expf(p3.x - newm); p3.y = __expf(p3.y - newm);
            p3.z = __expf(p3.z - newm); p3.w = __expf(p3.w - newm);
            float sum = p0.x + p0.y + p0.z + p0.w + p1.x + p1.y + p1.z + p1.w +
                        p2.x + p2.y + p2.z + p2.w + p3.x + p3.y + p3.z + p3.w;
            *(float4*)&Ps[base] = p0;
            *(float4*)&Ps[base + 4] = p1;
            *(float4*)&Ps[base + 8] = p2;
            *(float4*)&Ps[base + 12] = p3;
            sum += __shfl_xor_sync(0xffffffffu, sum, 1);
            sum += __shfl_xor_sync(0xffffffffu, sum, 2);
            if (sub == 0) {
                float a = __expf(m_old - newm);
                rowa[row] = a;
                rowl[row] = rowl[row] * a + sum;
                rowm[row] = newm;
            }
        }
        __syncthreads();

        // O = O*alpha + P @ V
#pragma unroll
        for (int ii = 0; ii < 4; ii++) {
            float a = rowa[i0 + ii];
            acc[ii][0] *= a; acc[ii][1] *= a; acc[ii][2] *= a; acc[ii][3] *= a;
        }
#pragma unroll 8
        for (int k = 0; k < 64; k++) {
            float4 vv = *(const float4*)&Vs[k * 68 + j0];
            float vb[4] = {vv.x, vv.y, vv.z, vv.w};
#pragma unroll
            for (int ii = 0; ii < 4; ii++) {
                float p = Ps[(i0 + ii) * 68 + k];
                acc[ii][0] = fmaf(p, vb[0], acc[ii][0]);
                acc[ii][1] = fmaf(p, vb[1], acc[ii][1]);
                acc[ii][2] = fmaf(p, vb[2], acc[ii][2]);
                acc[ii][3] = fmaf(p, vb[3], acc[ii][3]);
            }
        }
        __syncthreads();
    }

#pragma unroll
    for (int ii = 0; ii < 4; ii++) {
        float inv = 1.0f / rowl[i0 + ii];
        float4 o = make_float4(acc[ii][0] * inv, acc[ii][1] * inv,
                               acc[ii][2] * inv, acc[ii][3] * inv);
        *(float4*)(out + ((size_t)(b * LSEQ + q0 + i0 + ii) * DMODEL) + h * HDIM + j0) = o;
    }
}

// ---------------- LayerNorm: one block per row (D=1024) --------------------
__global__ __launch_bounds__(256) void ln_kernel(
    const float* __restrict__ X, const float* __restrict__ gam,
    const float* __restrict__ bet, float* __restrict__ Y) {
    __shared__ float red[8];
    __shared__ float sMean, sVar;
    const int row = blockIdx.x;
    const int tid = threadIdx.x;
    const float* x = X + (size_t)row * DMODEL;
    float4 v = *(const float4*)(x + tid * 4);
    float s = v.x + v.y + v.z + v.w;
#pragma unroll
    for (int o = 16; o; o >>= 1) s += __shfl_xor_sync(0xffffffffu, s, o);
    int w = tid >> 5, lane = tid & 31;
    if (lane == 0) red[w] = s;
    __syncthreads();
    if (tid == 0) {
        float t = 0;
#pragma unroll
        for (int i = 0; i < 8; i++) t += red[i];
        sMean = t * (1.0f / DMODEL);
    }
    __syncthreads();
    float m = sMean;
    float dx = v.x - m, dy = v.y - m, dz = v.z - m, dw = v.w - m;
    float q = dx * dx + dy * dy + dz * dz + dw * dw;
#pragma unroll
    for (int o = 16; o; o >>= 1) q += __shfl_xor_sync(0xffffffffu, q, o);
    if (lane == 0) red[w] = q;
    __syncthreads();
    if (tid == 0) {
        float t = 0;
#pragma unroll
        for (int i = 0; i < 8; i++) t += red[i];
        sVar = t * (1.0f / DMODEL);
    }
    __syncthreads();
    float inv = rsqrtf(sVar + LN_EPS);
    float4 gv = *(const float4*)(gam + tid * 4);
    float4 bv = *(const float4*)(bet + tid * 4);
    float4 o;
    o.x = dx * inv * gv.x + bv.x;
    o.y = dy * inv * gv.y + bv.y;
    o.z = dz * inv * gv.z + bv.z;
    o.w = dw * inv * gv.w + bv.w;
    *(float4*)(Y + (size_t)row * DMODEL + tid * 4) = o;
}

// ---------------- launch ----------------------------------------------------
extern "C" void kernel_launch(void* const* d_in, const int* in_sizes, int n_in,
                              void* d_out, int out_size) {
    const float* q  = (const float*)d_in[0];
    const float* kv = (const float*)d_in[1];
    const unsigned char* kvm = (const unsigned char*)d_in[2];
    const float* Wq = (const float*)d_in[3];
    const float* bq = (const float*)d_in[4];
    const float* Wk = (const float*)d_in[5];
    const float* bk = (const float*)d_in[6];
    const float* Wv = (const float*)d_in[7];
    const float* bv = (const float*)d_in[8];
    const float* Wo = (const float*)d_in[9];
    const float* bo = (const float*)d_in[10];
    const float* ln1g = (const float*)d_in[11];
    const float* ln1b = (const float*)d_in[12];
    const float* W1 = (const float*)d_in[13];
    const float* b1 = (const float*)d_in[14];
    const float* W2 = (const float*)d_in[15];
    const float* b2 = (const float*)d_in[16];
    const float* ln2g = (const float*)d_in[17];
    const float* ln2b = (const float*)d_in[18];
    float* out = (float*)d_out;

    float *qp, *kp, *vp, *att, *y, *x, *hbuf;
    int *allpad, *mstride;
    unsigned char* emask;
    cudaGetSymbolAddress((void**)&qp, g_qp);
    cudaGetSymbolAddress((void**)&kp, g_kp);
    cudaGetSymbolAddress((void**)&vp, g_vp);
    cudaGetSymbolAddress((void**)&att, g_att);
    cudaGetSymbolAddress((void**)&y, g_y);
    cudaGetSymbolAddress((void**)&x, g_x);
    cudaGetSymbolAddress((void**)&hbuf, g_h);
    cudaGetSymbolAddress((void**)&allpad, g_allpad);
    cudaGetSymbolAddress((void**)&emask, g_emask);
    cudaGetSymbolAddress((void**)&mstride, g_mstride);

    dim3 blk(256);
    dim3 gP(DMODEL / 128, MROWS / 128);     // (8, 64)
    dim3 gF1(DFF / 128, MROWS / 128);       // (32, 64)

    // QKV projections
    sgemm_kernel<<<gP, blk>>>(q,  Wq, bq, nullptr, qp, MROWS, DMODEL, DMODEL, 0);
    sgemm_kernel<<<gP, blk>>>(kv, Wk, bk, nullptr, kp, MROWS, DMODEL, DMODEL, 0);
    sgemm_kernel<<<gP, blk>>>(kv, Wv, bv, nullptr, vp, MROWS, DMODEL, DMODEL, 0);

    // mask normalization (dtype-robust) + all-pad fixup
    detect_mask_stride<<<1, 256>>>(kvm, mstride);
    mask_prep<<<BATCH, 256>>>(kvm, mstride, emask, allpad);

    // attention
    cudaFuncSetAttribute(attn_kernel, cudaFuncAttributeMaxDynamicSharedMemorySize,
                         ATT_SMEM_BYTES);
    attn_kernel<<<dim3(LSEQ / 64, NHEAD, BATCH), blk, ATT_SMEM_BYTES>>>(
        qp, kp, vp, emask, allpad, att);

    // O projection + residual, LN1
    sgemm_kernel<<<gP, blk>>>(att, Wo, bo, q, y, MROWS, DMODEL, DMODEL, 0);
    ln_kernel<<<MROWS, blk>>>(y, ln1g, ln1b, x);

    // FFN
    sgemm_kernel<<<gF1, blk>>>(x, W1, b1, nullptr, hbuf, MROWS, DFF, DMODEL, 1);
    sgemm_kernel<<<gP, blk>>>(hbuf, W2, b2, x, y, MROWS, DMODEL, DFF, 0);

    // LN2 -> output
    ln_kernel<<<MROWS, blk>>>(y, ln2g, ln2b, out);
}

// round 3
// speedup vs baseline: 2.2517x; 2.2517x over previous
#include <cuda_runtime.h>
#include <cuda_bf16.h>
#include <stdint.h>
#include <math.h>

// Problem constants
#define BATCH 8
#define LSEQ 1024
#define DMODEL 1024
#define NHEAD 16
#define HDIM 64
#define DFF 4096
#define MROWS (BATCH * LSEQ)   // 8192
#define ATT_SCALE 0.125f       // 64^-0.5
#define LN_EPS 1e-5f

// ---------------- scratch (device globals; no allocation allowed) ----------
__device__ float g_qp[MROWS * DMODEL];
__device__ float g_kp[MROWS * DMODEL];
__device__ float g_vp[MROWS * DMODEL];
__device__ float g_att[MROWS * DMODEL];
__device__ float g_y[MROWS * DMODEL];
__device__ float g_x[MROWS * DMODEL];
__device__ float g_h[(size_t)MROWS * DFF];
__device__ int g_allpad[BATCH];
__device__ unsigned char g_emask[BATCH * LSEQ];
__device__ int g_mstride[1];

// ---------------- TF32 tensor-core GEMM -------------------------------------
// C[M,N] = A[M,K] @ B[K,N] + bias (+relu) (+res)
// 128x128 block tile, BK=16, 256 threads (8 warps, 2x4 warp grid, 64x32 warp tile).
// cp.async double-buffered. A smem [m][k] stride 20, B smem [k][n] stride 136
// (both conflict-free for the mma fragment load patterns).
// Inputs rounded to tf32 with cvt.rna (unbiased) before mma.

#define ASTRIDE 20
#define BSTRIDE 136

__device__ __forceinline__ void cp16(float* smem, const float* g) {
    uint32_t s = (uint32_t)__cvta_generic_to_shared(smem);
    asm volatile("cp.async.cg.shared.global [%0], [%1], 16;\n" :: "r"(s), "l"(g));
}
__device__ __forceinline__ uint32_t f2tf(float x) {
    uint32_t r;
    asm("cvt.rna.tf32.f32 %0, %1;" : "=r"(r) : "f"(x));
    return r;
}
__device__ __forceinline__ void mma_tf32(float* c, const uint32_t* a, const uint32_t* b) {
    asm volatile(
        "mma.sync.aligned.m16n8k8.row.col.f32.tf32.tf32.f32 "
        "{%0,%1,%2,%3}, {%4,%5,%6,%7}, {%8,%9}, {%0,%1,%2,%3};"
        : "+f"(c[0]), "+f"(c[1]), "+f"(c[2]), "+f"(c[3])
        : "r"(a[0]), "r"(a[1]), "r"(a[2]), "r"(a[3]), "r"(b[0]), "r"(b[1]));
}

__global__ __launch_bounds__(256) void sgemm_tc(
    const float* __restrict__ A, const float* __restrict__ B,
    const float* __restrict__ bias, const float* __restrict__ res,
    float* __restrict__ C, int M, int N, int K, int doRelu) {
    __shared__ __align__(16) float As[2][128 * ASTRIDE];
    __shared__ __align__(16) float Bs[2][16 * BSTRIDE];

    const int tid = threadIdx.x;
    const int lane = tid & 31, warp = tid >> 5;
    const int wr = warp & 1, wc = warp >> 1;      // warp tile: rows wr*64, cols wc*32
    const int g = lane >> 2, tg = lane & 3;

    const int rowBlk = blockIdx.y * 128;
    const int colBlk = blockIdx.x * 128;

    // cp.async indexing
    const int am = tid >> 1;                      // 0..127
    const int ac = (tid & 1) * 8;                 // 0 or 8
    const int bk = tid >> 4;                      // 0..15
    const int bn = (tid & 15) * 8;                // 0..120
    const float* Agp = A + (size_t)(rowBlk + am) * K + ac;
    const float* Bgp = B + (size_t)bk * N + colBlk + bn;

    float acc[4][4][4];
#pragma unroll
    for (int i = 0; i < 4; i++)
#pragma unroll
        for (int j = 0; j < 4; j++)
#pragma unroll
            for (int v = 0; v < 4; v++) acc[i][j][v] = 0.f;

    const int nk = K / 16;

    // prologue: stage 0
    {
        cp16(&As[0][am * ASTRIDE + ac], Agp);
        cp16(&As[0][am * ASTRIDE + ac + 4], Agp + 4);
        cp16(&Bs[0][bk * BSTRIDE + bn], Bgp);
        cp16(&Bs[0][bk * BSTRIDE + bn + 4], Bgp + 4);
        asm volatile("cp.async.commit_group;");
    }

    for (int kt = 0; kt < nk; kt++) {
        if (kt + 1 < nk) {
            int st = (kt + 1) & 1;
            const float* ag = Agp + (kt + 1) * 16;
            const float* bg = Bgp + (size_t)(kt + 1) * 16 * N;
            cp16(&As[st][am * ASTRIDE + ac], ag);
            cp16(&As[st][am * ASTRIDE + ac + 4], ag + 4);
            cp16(&Bs[st][bk * BSTRIDE + bn], bg);
            cp16(&Bs[st][bk * BSTRIDE + bn + 4], bg + 4);
            asm volatile("cp.async.commit_group;");
            asm volatile("cp.async.wait_group 1;");
        } else {
            asm volatile("cp.async.wait_group 0;");
        }
        __syncthreads();

        const int st = kt & 1;
#pragma unroll
        for (int ks = 0; ks < 16; ks += 8) {
            uint32_t af[4][4], bf[4][2];
#pragma unroll
            for (int mi = 0; mi < 4; mi++) {
                const float* ap = &As[st][(wr * 64 + mi * 16 + g) * ASTRIDE + ks + tg];
                af[mi][0] = f2tf(ap[0]);
                af[mi][1] = f2tf(ap[8 * ASTRIDE]);
                af[mi][2] = f2tf(ap[4]);
                af[mi][3] = f2tf(ap[8 * ASTRIDE + 4]);
            }
#pragma unroll
            for (int ni = 0; ni < 4; ni++) {
                const float* bp = &Bs[st][(ks + tg) * BSTRIDE + wc * 32 + ni * 8 + g];
                bf[ni][0] = f2tf(bp[0]);
                bf[ni][1] = f2tf(bp[4 * BSTRIDE]);
            }
#pragma unroll
            for (int mi = 0; mi < 4; mi++)
#pragma unroll
                for (int ni = 0; ni < 4; ni++)
                    mma_tf32(acc[mi][ni], af[mi], bf[ni]);
        }
        __syncthreads();
    }

    // epilogue: c0,c1 -> (row g, col 2tg..2tg+1), c2,c3 -> (row g+8)
#pragma unroll
    for (int mi = 0; mi < 4; mi++) {
#pragma unroll
        for (int ni = 0; ni < 4; ni++) {
            int r0 = rowBlk + wr * 64 + mi * 16 + g;
            int c = colBlk + wc * 32 + ni * 8 + tg * 2;
            float2 bb = *(const float2*)(bias + c);
            float2 o0, o1;
            o0.x = acc[mi][ni][0] + bb.x;
            o0.y = acc[mi][ni][1] + bb.y;
            o1.x = acc[mi][ni][2] + bb.x;
            o1.y = acc[mi][ni][3] + bb.y;
            if (doRelu) {
                o0.x = fmaxf(o0.x, 0.f); o0.y = fmaxf(o0.y, 0.f);
                o1.x = fmaxf(o1.x, 0.f); o1.y = fmaxf(o1.y, 0.f);
            }
            if (res) {
                float2 r0v = *(const float2*)(res + (size_t)r0 * N + c);
                float2 r1v = *(const float2*)(res + (size_t)(r0 + 8) * N + c);
                o0.x += r0v.x; o0.y += r0v.y;
                o1.x += r1v.x; o1.y += r1v.y;
            }
            *(float2*)(C + (size_t)r0 * N + c) = o0;
            *(float2*)(C + (size_t)(r0 + 8) * N + c) = o1;
        }
    }
}

// ---------------- mask dtype detection + normalization ---------------------
__global__ void detect_mask_stride(const unsigned char* __restrict__ m, int* stride_out) {
    __shared__ int any;
    if (threadIdx.x == 0) any = 0;
    __syncthreads();
    int a = 0;
    for (int j = threadIdx.x; j < 2048; j += 256) a |= m[j * 4 + 1];
    if (a) atomicOr(&any, 1);
    __syncthreads();
    if (threadIdx.x == 0) *stride_out = any ? 1 : 4;
}

__global__ void mask_prep(const unsigned char* __restrict__ m,
                          const int* __restrict__ stridep,
                          unsigned char* __restrict__ em, int* __restrict__ allpad) {
    int b = blockIdx.x;
    int st = *stridep;
    int ok = 1;
    for (int j = threadIdx.x; j < LSEQ; j += 256) {
        unsigned char v = (m[(size_t)(b * LSEQ + j) * st] != 0) ? 1 : 0;
        em[b * LSEQ + j] = v;
        ok &= (int)v;
    }
    ok = __syncthreads_and(ok);
    if (threadIdx.x == 0) allpad[b] = ok;
}

// ---------------- flash-style attention (fp32) ------------------------------
#define ATT_SMEM_FLOATS (4 * 64 * 68 + 4 * 64)
#define ATT_SMEM_BYTES (ATT_SMEM_FLOATS * 4)

__global__ __launch_bounds__(256) void attn_kernel(
    const float* __restrict__ qp, const float* __restrict__ kp,
    const float* __restrict__ vp, const unsigned char* __restrict__ em,
    const int* __restrict__ allpad, float* __restrict__ out) {
    extern __shared__ float sm[];
    float* Qst = sm;                    // [d][i], stride 68
    float* Kst = sm + 64 * 68;          // [d][j]
    float* Vs  = sm + 2 * 64 * 68;      // [k][c]
    float* Ps  = sm + 3 * 64 * 68;      // [i][k]
    float* rowm = sm + 4 * 64 * 68;
    float* rowl = rowm + 64;
    float* rowa = rowl + 64;
    float* mk   = rowa + 64;

    const int b = blockIdx.z, h = blockIdx.y, q0 = blockIdx.x * 64;
    const int tid = threadIdx.x;
    const int tx = tid & 15, ty = tid >> 4;
    const int i0 = ty * 4, j0 = tx * 4;
    const int ap = allpad[b];
    const size_t qoff = ((size_t)(b * LSEQ + q0) * DMODEL) + h * HDIM;

    for (int t = tid; t < 64 * 16; t += 256) {
        int i = t >> 4, c4 = (t & 15) * 4;
        float4 v = *(const float4*)(qp + qoff + (size_t)i * DMODEL + c4);
        Qst[(c4 + 0) * 68 + i] = v.x;
        Qst[(c4 + 1) * 68 + i] = v.y;
        Qst[(c4 + 2) * 68 + i] = v.z;
        Qst[(c4 + 3) * 68 + i] = v.w;
    }
    if (tid < 64) { rowm[tid] = -1e30f; rowl[tid] = 0.f; }
    float acc[4][4] = {};

    for (int kt = 0; kt < 16; kt++) {
        const size_t koff = ((size_t)(b * LSEQ + kt * 64) * DMODEL) + h * HDIM;
        for (int t = tid; t < 64 * 16; t += 256) {
            int j = t >> 4, c4 = (t & 15) * 4;
            float4 kvv = *(const float4*)(kp + koff + (size_t)j * DMODEL + c4);
            Kst[(c4 + 0) * 68 + j] = kvv.x;
            Kst[(c4 + 1) * 68 + j] = kvv.y;
            Kst[(c4 + 2) * 68 + j] = kvv.z;
            Kst[(c4 + 3) * 68 + j] = kvv.w;
            float4 vvv = *(const float4*)(vp + koff + (size_t)j * DMODEL + c4);
            *(float4*)&Vs[j * 68 + c4] = vvv;
        }
        if (tid < 64) {
            int kidx = kt * 64 + tid;
            int msk = em[b * LSEQ + kidx];
            if (ap && kidx == LSEQ - 1) msk = 0;
            mk[tid] = msk ? 1.0f : 0.0f;
        }
        __syncthreads();

        float s[4][4] = {};
#pragma unroll 8
        for (int d = 0; d < 64; d++) {
            float4 qv = *(const float4*)&Qst[d * 68 + i0];
            float4 kvv = *(const float4*)&Kst[d * 68 + j0];
            float qa[4] = {qv.x, qv.y, qv.z, qv.w};
            float kb[4] = {kvv.x, kvv.y, kvv.z, kvv.w};
#pragma unroll
            for (int ii = 0; ii < 4; ii++)
#pragma unroll
                for (int jj = 0; jj < 4; jj++)
                    s[ii][jj] = fmaf(qa[ii], kb[jj], s[ii][jj]);
        }
#pragma unroll
        for (int ii = 0; ii < 4; ii++) {
            float4 o;
            float* pp = (float*)&o;
#pragma unroll
            for (int jj = 0; jj < 4; jj++) {
                float v = s[ii][jj] * ATT_SCALE;
                pp[jj] = (mk[j0 + jj] != 0.f) ? -10000.0f : v;
            }
            *(float4*)&Ps[(i0 + ii) * 68 + j0] = o;
        }
        __syncthreads();

        {
            int row = tid >> 2, sub = tid & 3;
            int base = row * 68 + sub * 16;
            float4 p0 = *(float4*)&Ps[base];
            float4 p1 = *(float4*)&Ps[base + 4];
            float4 p2 = *(float4*)&Ps[base + 8];
            float4 p3 = *(float4*)&Ps[base + 12];
            float tm = fmaxf(fmaxf(fmaxf(p0.x, p0.y), fmaxf(p0.z, p0.w)),
                             fmaxf(fmaxf(p1.x, p1.y), fmaxf(p1.z, p1.w)));
            tm = fmaxf(tm, fmaxf(fmaxf(fmaxf(p2.x, p2.y), fmaxf(p2.z, p2.w)),
                                 fmaxf(fmaxf(p3.x, p3.y), fmaxf(p3.z, p3.w))));
            tm = fmaxf(tm, __shfl_xor_sync(0xffffffffu, tm, 1));
            tm = fmaxf(tm, __shfl_xor_sync(0xffffffffu, tm, 2));
            float m_old = rowm[row];
            float newm = fmaxf(m_old, tm);
            p0.x = __expf(p0.x - newm); p0.y = __expf(p0.y - newm);
            p0.z = __expf(p0.z - newm); p0.w = __expf(p0.w - newm);
            p1.x = __expf(p1.x - newm); p1.y = __expf(p1.y - newm);
            p1.z = __expf(p1.z - newm); p1.w = __expf(p1.w - newm);
            p2.x = __expf(p2.x - newm); p2.y = __expf(p2.y - newm);
            p2.z = __expf(p2.z - newm); p2.w = __expf(p2.w - newm);
            p3.x = __expf(p3.x - newm); p3.y = __expf(p3.y - newm);
            p3.z = __expf(p3.z - newm); p3.w = __expf(p3.w - newm);
            float sum = p0.x + p0.y + p0.z + p0.w + p1.x + p1.y + p1.z + p1.w +
                        p2.x + p2.y + p2.z + p2.w + p3.x + p3.y + p3.z + p3.w;
            *(float4*)&Ps[base] = p0;
            *(float4*)&Ps[base + 4] = p1;
            *(float4*)&Ps[base + 8] = p2;
            *(float4*)&Ps[base + 12] = p3;
            sum += __shfl_xor_sync(0xffffffffu, sum, 1);
            sum += __shfl_xor_sync(0xffffffffu, sum, 2);
            if (sub == 0) {
                float a = __expf(m_old - newm);
                rowa[row] = a;
                rowl[row] = rowl[row] * a + sum;
                rowm[row] = newm;
            }
        }
        __syncthreads();

#pragma unroll
        for (int ii = 0; ii < 4; ii++) {
            float a = rowa[i0 + ii];
            acc[ii][0] *= a; acc[ii][1] *= a; acc[ii][2] *= a; acc[ii][3] *= a;
        }
#pragma unroll 8
        for (int k = 0; k < 64; k++) {
            float4 vv = *(const float4*)&Vs[k * 68 + j0];
            float vb[4] = {vv.x, vv.y, vv.z, vv.w};
#pragma unroll
            for (int ii = 0; ii < 4; ii++) {
                float p = Ps[(i0 + ii) * 68 + k];
                acc[ii][0] = fmaf(p, vb[0], acc[ii][0]);
                acc[ii][1] = fmaf(p, vb[1], acc[ii][1]);
                acc[ii][2] = fmaf(p, vb[2], acc[ii][2]);
                acc[ii][3] = fmaf(p, vb[3], acc[ii][3]);
            }
        }
        __syncthreads();
    }

#pragma unroll
    for (int ii = 0; ii < 4; ii++) {
        float inv = 1.0f / rowl[i0 + ii];
        float4 o = make_float4(acc[ii][0] * inv, acc[ii][1] * inv,
                               acc[ii][2] * inv, acc[ii][3] * inv);
        *(float4*)(out + ((size_t)(b * LSEQ + q0 + i0 + ii) * DMODEL) + h * HDIM + j0) = o;
    }
}

// ---------------- LayerNorm: one block per row (D=1024) --------------------
__global__ __launch_bounds__(256) void ln_kernel(
    const float* __restrict__ X, const float* __restrict__ gam,
    const float* __restrict__ bet, float* __restrict__ Y) {
    __shared__ float red[8];
    __shared__ float sMean, sVar;
    const int row = blockIdx.x;
    const int tid = threadIdx.x;
    const float* x = X + (size_t)row * DMODEL;
    float4 v = *(const float4*)(x + tid * 4);
    float s = v.x + v.y + v.z + v.w;
#pragma unroll
    for (int o = 16; o; o >>= 1) s += __shfl_xor_sync(0xffffffffu, s, o);
    int w = tid >> 5, lane = tid & 31;
    if (lane == 0) red[w] = s;
    __syncthreads();
    if (tid == 0) {
        float t = 0;
#pragma unroll
        for (int i = 0; i < 8; i++) t += red[i];
        sMean = t * (1.0f / DMODEL);
    }
    __syncthreads();
    float m = sMean;
    float dx = v.x - m, dy = v.y - m, dz = v.z - m, dw = v.w - m;
    float q = dx * dx + dy * dy + dz * dz + dw * dw;
#pragma unroll
    for (int o = 16; o; o >>= 1) q += __shfl_xor_sync(0xffffffffu, q, o);
    if (lane == 0) red[w] = q;
    __syncthreads();
    if (tid == 0) {
        float t = 0;
#pragma unroll
        for (int i = 0; i < 8; i++) t += red[i];
        sVar = t * (1.0f / DMODEL);
    }
    __syncthreads();
    float inv = rsqrtf(sVar + LN_EPS);
    float4 gv = *(const float4*)(gam + tid * 4);
    float4 bv = *(const float4*)(bet + tid * 4);
    float4 o;
    o.x = dx * inv * gv.x + bv.x;
    o.y = dy * inv * gv.y + bv.y;
    o.z = dz * inv * gv.z + bv.z;
    o.w = dw * inv * gv.w + bv.w;
    *(float4*)(Y + (size_t)row * DMODEL + tid * 4) = o;
}

// ---------------- launch ----------------------------------------------------
extern "C" void kernel_launch(void* const* d_in, const int* in_sizes, int n_in,
                              void* d_out, int out_size) {
    const float* q  = (const float*)d_in[0];
    const float* kv = (const float*)d_in[1];
    const unsigned char* kvm = (const unsigned char*)d_in[2];
    const float* Wq = (const float*)d_in[3];
    const float* bq = (const float*)d_in[4];
    const float* Wk = (const float*)d_in[5];
    const float* bk = (const float*)d_in[6];
    const float* Wv = (const float*)d_in[7];
    const float* bv = (const float*)d_in[8];
    const float* Wo = (const float*)d_in[9];
    const float* bo = (const float*)d_in[10];
    const float* ln1g = (const float*)d_in[11];
    const float* ln1b = (const float*)d_in[12];
    const float* W1 = (const float*)d_in[13];
    const float* b1 = (const float*)d_in[14];
    const float* W2 = (const float*)d_in[15];
    const float* b2 = (const float*)d_in[16];
    const float* ln2g = (const float*)d_in[17];
    const float* ln2b = (const float*)d_in[18];
    float* out = (float*)d_out;

    float *qp, *kp, *vp, *att, *y, *x, *hbuf;
    int *allpad, *mstride;
    unsigned char* emask;
    cudaGetSymbolAddress((void**)&qp, g_qp);
    cudaGetSymbolAddress((void**)&kp, g_kp);
    cudaGetSymbolAddress((void**)&vp, g_vp);
    cudaGetSymbolAddress((void**)&att, g_att);
    cudaGetSymbolAddress((void**)&y, g_y);
    cudaGetSymbolAddress((void**)&x, g_x);
    cudaGetSymbolAddress((void**)&hbuf, g_h);
    cudaGetSymbolAddress((void**)&allpad, g_allpad);
    cudaGetSymbolAddress((void**)&emask, g_emask);
    cudaGetSymbolAddress((void**)&mstride, g_mstride);

    dim3 blk(256);
    dim3 gP(DMODEL / 128, MROWS / 128);     // (8, 64)
    dim3 gF1(DFF / 128, MROWS / 128);       // (32, 64)

    // mask normalization first (shifts big kernels into the ncu -s window)
    detect_mask_stride<<<1, 256>>>(kvm, mstride);
    mask_prep<<<BATCH, 256>>>(kvm, mstride, emask, allpad);

    // QKV projections (tf32 tensor cores)
    sgemm_tc<<<gP, blk>>>(q,  Wq, bq, nullptr, qp, MROWS, DMODEL, DMODEL, 0);
    sgemm_tc<<<gP, blk>>>(kv, Wk, bk, nullptr, kp, MROWS, DMODEL, DMODEL, 0);
    sgemm_tc<<<gP, blk>>>(kv, Wv, bv, nullptr, vp, MROWS, DMODEL, DMODEL, 0);

    // attention
    cudaFuncSetAttribute(attn_kernel, cudaFuncAttributeMaxDynamicSharedMemorySize,
                         ATT_SMEM_BYTES);
    attn_kernel<<<dim3(LSEQ / 64, NHEAD, BATCH), blk, ATT_SMEM_BYTES>>>(
        qp, kp, vp, emask, allpad, att);

    // O projection + residual, LN1
    sgemm_tc<<<gP, blk>>>(att, Wo, bo, q, y, MROWS, DMODEL, DMODEL, 0);
    ln_kernel<<<MROWS, blk>>>(y, ln1g, ln1b, x);

    // FFN
    sgemm_tc<<<gF1, blk>>>(x, W1, b1, nullptr, hbuf, MROWS, DFF, DMODEL, 1);
    sgemm_tc<<<gP, blk>>>(hbuf, W2, b2, x, y, MROWS, DMODEL, DFF, 0);

    // LN2 -> output
    ln_kernel<<<MROWS, blk>>>(y, ln2g, ln2b, out);
}

// round 4
// speedup vs baseline: 2.4737x; 1.0986x over previous
#include <cuda_runtime.h>
#include <cuda_bf16.h>
#include <stdint.h>
#include <math.h>

// Problem constants
#define BATCH 8
#define LSEQ 1024
#define DMODEL 1024
#define NHEAD 16
#define HDIM 64
#define DFF 4096
#define MROWS (BATCH * LSEQ)   // 8192
#define ATT_SCALE 0.125f       // 64^-0.5
#define LN_EPS 1e-5f

// ---------------- scratch (device globals; no allocation allowed) ----------
__device__ float g_qp[MROWS * DMODEL];
__device__ float g_kp[MROWS * DMODEL];
__device__ float g_vp[MROWS * DMODEL];
__device__ float g_att[MROWS * DMODEL];
__device__ float g_y[MROWS * DMODEL];
__device__ float g_x[MROWS * DMODEL];
__device__ float g_xr[MROWS * DMODEL];
__device__ float g_h[(size_t)MROWS * DFF];
__device__ float g_qr[MROWS * DMODEL];
__device__ float g_kvr[MROWS * DMODEL];
__device__ float g_wqr[DMODEL * DMODEL];
__device__ float g_wkr[DMODEL * DMODEL];
__device__ float g_wvr[DMODEL * DMODEL];
__device__ float g_wor[DMODEL * DMODEL];
__device__ float g_w1r[DMODEL * DFF];
__device__ float g_w2r[DFF * DMODEL];
__device__ int g_allpad[BATCH];
__device__ unsigned char g_emask[BATCH * LSEQ];
__device__ int g_mstride[1];

// ---------------- helpers ----------------------------------------------------
__device__ __forceinline__ void cp16(float* smem, const float* g) {
    uint32_t s = (uint32_t)__cvta_generic_to_shared(smem);
    asm volatile("cp.async.cg.shared.global [%0], [%1], 16;\n" :: "r"(s), "l"(g));
}
__device__ __forceinline__ uint32_t f2tf(float x) {
    uint32_t r;
    asm("cvt.rna.tf32.f32 %0, %1;" : "=r"(r) : "f"(x));
    return r;
}
__device__ __forceinline__ float rtf(float x) { return __uint_as_float(f2tf(x)); }
__device__ __forceinline__ void mma_tf32(float* c, const uint32_t* a, const uint32_t* b) {
    asm volatile(
        "mma.sync.aligned.m16n8k8.row.col.f32.tf32.tf32.f32 "
        "{%0,%1,%2,%3}, {%4,%5,%6,%7}, {%8,%9}, {%0,%1,%2,%3};"
        : "+f"(c[0]), "+f"(c[1]), "+f"(c[2]), "+f"(c[3])
        : "r"(a[0]), "r"(a[1]), "r"(a[2]), "r"(a[3]), "r"(b[0]), "r"(b[1]));
}

// ---------------- bulk tf32 rounding -----------------------------------------
__global__ __launch_bounds__(256) void round_tf32(const float* __restrict__ in,
                                                  float* __restrict__ out, int n4) {
    int i = blockIdx.x * 256 + threadIdx.x;
    if (i < n4) {
        float4 v = ((const float4*)in)[i];
        v.x = rtf(v.x); v.y = rtf(v.y); v.z = rtf(v.z); v.w = rtf(v.w);
        ((float4*)out)[i] = v;
    }
}

// ---------------- TF32 tensor-core GEMM -------------------------------------
// C[M,N] = A[M,K] @ B[K,N] + bias (+relu) (+res) (+roundOut)
// Operands must already be tf32-rounded. No cvt in the mainloop.
#define ASTRIDE 20
#define BSTRIDE 136

__global__ __launch_bounds__(256) void sgemm_tc(
    const float* __restrict__ A, const float* __restrict__ B,
    const float* __restrict__ bias, const float* __restrict__ res,
    float* __restrict__ C, int M, int N, int K, int doRelu, int roundOut) {
    __shared__ __align__(16) float As[2][128 * ASTRIDE];
    __shared__ __align__(16) float Bs[2][16 * BSTRIDE];

    const int tid = threadIdx.x;
    const int lane = tid & 31, warp = tid >> 5;
    const int wr = warp & 1, wc = warp >> 1;
    const int g = lane >> 2, tg = lane & 3;

    const int rowBlk = blockIdx.y * 128;
    const int colBlk = blockIdx.x * 128;

    const int am = tid >> 1;
    const int ac = (tid & 1) * 8;
    const int bk = tid >> 4;
    const int bn = (tid & 15) * 8;
    const float* Agp = A + (size_t)(rowBlk + am) * K + ac;
    const float* Bgp = B + (size_t)bk * N + colBlk + bn;

    float acc[4][4][4];
#pragma unroll
    for (int i = 0; i < 4; i++)
#pragma unroll
        for (int j = 0; j < 4; j++)
#pragma unroll
            for (int v = 0; v < 4; v++) acc[i][j][v] = 0.f;

    const int nk = K / 16;

    {
        cp16(&As[0][am * ASTRIDE + ac], Agp);
        cp16(&As[0][am * ASTRIDE + ac + 4], Agp + 4);
        cp16(&Bs[0][bk * BSTRIDE + bn], Bgp);
        cp16(&Bs[0][bk * BSTRIDE + bn + 4], Bgp + 4);
        asm volatile("cp.async.commit_group;");
    }

    for (int kt = 0; kt < nk; kt++) {
        if (kt + 1 < nk) {
            int st = (kt + 1) & 1;
            const float* ag = Agp + (kt + 1) * 16;
            const float* bg = Bgp + (size_t)(kt + 1) * 16 * N;
            cp16(&As[st][am * ASTRIDE + ac], ag);
            cp16(&As[st][am * ASTRIDE + ac + 4], ag + 4);
            cp16(&Bs[st][bk * BSTRIDE + bn], bg);
            cp16(&Bs[st][bk * BSTRIDE + bn + 4], bg + 4);
            asm volatile("cp.async.commit_group;");
            asm volatile("cp.async.wait_group 1;");
        } else {
            asm volatile("cp.async.wait_group 0;");
        }
        __syncthreads();

        const int st = kt & 1;
#pragma unroll
        for (int ks = 0; ks < 16; ks += 8) {
            uint32_t af[4][4], bf[4][2];
#pragma unroll
            for (int mi = 0; mi < 4; mi++) {
                const float* ap = &As[st][(wr * 64 + mi * 16 + g) * ASTRIDE + ks + tg];
                af[mi][0] = __float_as_uint(ap[0]);
                af[mi][1] = __float_as_uint(ap[8 * ASTRIDE]);
                af[mi][2] = __float_as_uint(ap[4]);
                af[mi][3] = __float_as_uint(ap[8 * ASTRIDE + 4]);
            }
#pragma unroll
            for (int ni = 0; ni < 4; ni++) {
                const float* bp = &Bs[st][(ks + tg) * BSTRIDE + wc * 32 + ni * 8 + g];
                bf[ni][0] = __float_as_uint(bp[0]);
                bf[ni][1] = __float_as_uint(bp[4 * BSTRIDE]);
            }
#pragma unroll
            for (int mi = 0; mi < 4; mi++)
#pragma unroll
                for (int ni = 0; ni < 4; ni++)
                    mma_tf32(acc[mi][ni], af[mi], bf[ni]);
        }
        __syncthreads();
    }

#pragma unroll
    for (int mi = 0; mi < 4; mi++) {
#pragma unroll
        for (int ni = 0; ni < 4; ni++) {
            int r0 = rowBlk + wr * 64 + mi * 16 + g;
            int c = colBlk + wc * 32 + ni * 8 + tg * 2;
            float2 bb = *(const float2*)(bias + c);
            float2 o0, o1;
            o0.x = acc[mi][ni][0] + bb.x;
            o0.y = acc[mi][ni][1] + bb.y;
            o1.x = acc[mi][ni][2] + bb.x;
            o1.y = acc[mi][ni][3] + bb.y;
            if (doRelu) {
                o0.x = fmaxf(o0.x, 0.f); o0.y = fmaxf(o0.y, 0.f);
                o1.x = fmaxf(o1.x, 0.f); o1.y = fmaxf(o1.y, 0.f);
            }
            if (res) {
                float2 r0v = *(const float2*)(res + (size_t)r0 * N + c);
                float2 r1v = *(const float2*)(res + (size_t)(r0 + 8) * N + c);
                o0.x += r0v.x; o0.y += r0v.y;
                o1.x += r1v.x; o1.y += r1v.y;
            }
            if (roundOut) {
                o0.x = rtf(o0.x); o0.y = rtf(o0.y);
                o1.x = rtf(o1.x); o1.y = rtf(o1.y);
            }
            *(float2*)(C + (size_t)r0 * N + c) = o0;
            *(float2*)(C + (size_t)(r0 + 8) * N + c) = o1;
        }
    }
}

// ---------------- mask dtype detection + normalization ---------------------
__global__ void detect_mask_stride(const unsigned char* __restrict__ m, int* stride_out) {
    __shared__ int any;
    if (threadIdx.x == 0) any = 0;
    __syncthreads();
    int a = 0;
    for (int j = threadIdx.x; j < 2048; j += 256) a |= m[j * 4 + 1];
    if (a) atomicOr(&any, 1);
    __syncthreads();
    if (threadIdx.x == 0) *stride_out = any ? 1 : 4;
}

__global__ void mask_prep(const unsigned char* __restrict__ m,
                          const int* __restrict__ stridep,
                          unsigned char* __restrict__ em, int* __restrict__ allpad) {
    int b = blockIdx.x;
    int st = *stridep;
    int ok = 1;
    for (int j = threadIdx.x; j < LSEQ; j += 256) {
        unsigned char v = (m[(size_t)(b * LSEQ + j) * st] != 0) ? 1 : 0;
        em[b * LSEQ + j] = v;
        ok &= (int)v;
    }
    ok = __syncthreads_and(ok);
    if (threadIdx.x == 0) allpad[b] = ok;
}

// ---------------- TF32 tensor-core flash attention --------------------------
// qp/kp/vp are already tf32-rounded (QKV gemm roundOut=1).
// Layouts: Qst/Kst [d][i] stride 68 (== mma A/B frags for S=QK^T),
//          Vs [k][d] stride 68 (== B frag for PV), Ps [i][k] stride 68 (== A frag).
#define ATT_SMEM_FLOATS (4 * 64 * 68 + 4 * 64)
#define ATT_SMEM_BYTES (ATT_SMEM_FLOATS * 4)

__global__ __launch_bounds__(256) void attn_tc(
    const float* __restrict__ qp, const float* __restrict__ kp,
    const float* __restrict__ vp, const unsigned char* __restrict__ em,
    const int* __restrict__ allpad, float* __restrict__ out) {
    extern __shared__ float sm[];
    float* Qst = sm;                    // [d][i], stride 68
    float* Kst = sm + 64 * 68;          // [d][j]
    float* Vs  = sm + 2 * 64 * 68;      // [k][c]
    float* Ps  = sm + 3 * 64 * 68;      // [i][k]
    float* rowm = sm + 4 * 64 * 68;
    float* rowl = rowm + 64;
    float* rowa = rowl + 64;
    float* mk   = rowa + 64;

    const int b = blockIdx.z, h = blockIdx.y, q0 = blockIdx.x * 64;
    const int tid = threadIdx.x;
    const int lane = tid & 31, warp = tid >> 5;
    const int g = lane >> 2, tg = lane & 3;
    const int wr = warp & 1, wc = warp >> 1;   // warp tile 32(m) x 16(n)
    const int ap = allpad[b];
    const size_t qoff = ((size_t)(b * LSEQ + q0) * DMODEL) + h * HDIM;

    for (int t = tid; t < 64 * 16; t += 256) {
        int i = t >> 4, c4 = (t & 15) * 4;
        float4 v = *(const float4*)(qp + qoff + (size_t)i * DMODEL + c4);
        Qst[(c4 + 0) * 68 + i] = v.x;
        Qst[(c4 + 1) * 68 + i] = v.y;
        Qst[(c4 + 2) * 68 + i] = v.z;
        Qst[(c4 + 3) * 68 + i] = v.w;
    }
    if (tid < 64) { rowm[tid] = -1e30f; rowl[tid] = 0.f; }

    float acc[2][2][4];
#pragma unroll
    for (int mi = 0; mi < 2; mi++)
#pragma unroll
        for (int ni = 0; ni < 2; ni++)
#pragma unroll
            for (int v = 0; v < 4; v++) acc[mi][ni][v] = 0.f;

    for (int kt = 0; kt < 16; kt++) {
        const size_t koff = ((size_t)(b * LSEQ + kt * 64) * DMODEL) + h * HDIM;
        for (int t = tid; t < 64 * 16; t += 256) {
            int j = t >> 4, c4 = (t & 15) * 4;
            float4 kvv = *(const float4*)(kp + koff + (size_t)j * DMODEL + c4);
            Kst[(c4 + 0) * 68 + j] = kvv.x;
            Kst[(c4 + 1) * 68 + j] = kvv.y;
            Kst[(c4 + 2) * 68 + j] = kvv.z;
            Kst[(c4 + 3) * 68 + j] = kvv.w;
            float4 vvv = *(const float4*)(vp + koff + (size_t)j * DMODEL + c4);
            *(float4*)&Vs[j * 68 + c4] = vvv;
        }
        if (tid < 64) {
            int kidx = kt * 64 + tid;
            int msk = em[b * LSEQ + kidx];
            if (ap && kidx == LSEQ - 1) msk = 0;
            mk[tid] = msk ? 1.0f : 0.0f;
        }
        __syncthreads();

        // ---- S = Q K^T via mma ----
        float s[2][2][4];
#pragma unroll
        for (int mi = 0; mi < 2; mi++)
#pragma unroll
            for (int ni = 0; ni < 2; ni++)
#pragma unroll
                for (int v = 0; v < 4; v++) s[mi][ni][v] = 0.f;
#pragma unroll
        for (int ks = 0; ks < 64; ks += 8) {
            uint32_t af[2][4], bf[2][2];
#pragma unroll
            for (int mi = 0; mi < 2; mi++) {
                int rr = wr * 32 + mi * 16 + g;
                af[mi][0] = __float_as_uint(Qst[(ks + tg) * 68 + rr]);
                af[mi][1] = __float_as_uint(Qst[(ks + tg) * 68 + rr + 8]);
                af[mi][2] = __float_as_uint(Qst[(ks + tg + 4) * 68 + rr]);
                af[mi][3] = __float_as_uint(Qst[(ks + tg + 4) * 68 + rr + 8]);
            }
#pragma unroll
            for (int ni = 0; ni < 2; ni++) {
                int cc = wc * 16 + ni * 8 + g;
                bf[ni][0] = __float_as_uint(Kst[(ks + tg) * 68 + cc]);
                bf[ni][1] = __float_as_uint(Kst[(ks + tg + 4) * 68 + cc]);
            }
#pragma unroll
            for (int mi = 0; mi < 2; mi++)
#pragma unroll
                for (int ni = 0; ni < 2; ni++)
                    mma_tf32(s[mi][ni], af[mi], bf[ni]);
        }
        // scatter scale+mask into Ps
#pragma unroll
        for (int mi = 0; mi < 2; mi++) {
            int rr = wr * 32 + mi * 16 + g;
#pragma unroll
            for (int ni = 0; ni < 2; ni++) {
                int cc = wc * 16 + ni * 8 + tg * 2;
                float m0 = mk[cc], m1 = mk[cc + 1];
                Ps[rr * 68 + cc]       = (m0 != 0.f) ? -10000.f : s[mi][ni][0] * ATT_SCALE;
                Ps[rr * 68 + cc + 1]   = (m1 != 0.f) ? -10000.f : s[mi][ni][1] * ATT_SCALE;
                Ps[(rr + 8) * 68 + cc]     = (m0 != 0.f) ? -10000.f : s[mi][ni][2] * ATT_SCALE;
                Ps[(rr + 8) * 68 + cc + 1] = (m1 != 0.f) ? -10000.f : s[mi][ni][3] * ATT_SCALE;
            }
        }
        __syncthreads();

        // ---- online softmax (fp32; rounds P to tf32 before summing) ----
        {
            int row = tid >> 2, sub = tid & 3;
            int base = row * 68 + sub * 16;
            float4 p0 = *(float4*)&Ps[base];
            float4 p1 = *(float4*)&Ps[base + 4];
            float4 p2 = *(float4*)&Ps[base + 8];
            float4 p3 = *(float4*)&Ps[base + 12];
            float tm = fmaxf(fmaxf(fmaxf(p0.x, p0.y), fmaxf(p0.z, p0.w)),
                             fmaxf(fmaxf(p1.x, p1.y), fmaxf(p1.z, p1.w)));
            tm = fmaxf(tm, fmaxf(fmaxf(fmaxf(p2.x, p2.y), fmaxf(p2.z, p2.w)),
                                 fmaxf(fmaxf(p3.x, p3.y), fmaxf(p3.z, p3.w))));
            tm = fmaxf(tm, __shfl_xor_sync(0xffffffffu, tm, 1));
            tm = fmaxf(tm, __shfl_xor_sync(0xffffffffu, tm, 2));
            float m_old = rowm[row];
            float newm = fmaxf(m_old, tm);
            p0.x = rtf(__expf(p0.x - newm)); p0.y = rtf(__expf(p0.y - newm));
            p0.z = rtf(__expf(p0.z - newm)); p0.w = rtf(__expf(p0.w - newm));
            p1.x = rtf(__expf(p1.x - newm)); p1.y = rtf(__expf(p1.y - newm));
            p1.z = rtf(__expf(p1.z - newm)); p1.w = rtf(__expf(p1.w - newm));
            p2.x = rtf(__expf(p2.x - newm)); p2.y = rtf(__expf(p2.y - newm));
            p2.z = rtf(__expf(p2.z - newm)); p2.w = rtf(__expf(p2.w - newm));
            p3.x = rtf(__expf(p3.x - newm)); p3.y = rtf(__expf(p3.y - newm));
            p3.z = rtf(__expf(p3.z - newm)); p3.w = rtf(__expf(p3.w - newm));
            float sum = p0.x + p0.y + p0.z + p0.w + p1.x + p1.y + p1.z + p1.w +
                        p2.x + p2.y + p2.z + p2.w + p3.x + p3.y + p3.z + p3.w;
            *(float4*)&Ps[base] = p0;
            *(float4*)&Ps[base + 4] = p1;
            *(float4*)&Ps[base + 8] = p2;
            *(float4*)&Ps[base + 12] = p3;
            sum += __shfl_xor_sync(0xffffffffu, sum, 1);
            sum += __shfl_xor_sync(0xffffffffu, sum, 2);
            if (sub == 0) {
                float a = __expf(m_old - newm);
                rowa[row] = a;
                rowl[row] = rowl[row] * a + sum;
                rowm[row] = newm;
            }
        }
        __syncthreads();

        // ---- O = O*alpha + P @ V via mma ----
#pragma unroll
        for (int mi = 0; mi < 2; mi++) {
            int rr = wr * 32 + mi * 16 + g;
            float a0 = rowa[rr], a8 = rowa[rr + 8];
#pragma unroll
            for (int ni = 0; ni < 2; ni++) {
                acc[mi][ni][0] *= a0; acc[mi][ni][1] *= a0;
                acc[mi][ni][2] *= a8; acc[mi][ni][3] *= a8;
            }
        }
#pragma unroll
        for (int ks = 0; ks < 64; ks += 8) {
            uint32_t af[2][4], bf[2][2];
#pragma unroll
            for (int mi = 0; mi < 2; mi++) {
                int rr = wr * 32 + mi * 16 + g;
                af[mi][0] = __float_as_uint(Ps[rr * 68 + ks + tg]);
                af[mi][1] = __float_as_uint(Ps[(rr + 8) * 68 + ks + tg]);
                af[mi][2] = __float_as_uint(Ps[rr * 68 + ks + tg + 4]);
                af[mi][3] = __float_as_uint(Ps[(rr + 8) * 68 + ks + tg + 4]);
            }
#pragma unroll
            for (int ni = 0; ni < 2; ni++) {
                int cc = wc * 16 + ni * 8 + g;
                bf[ni][0] = __float_as_uint(Vs[(ks + tg) * 68 + cc]);
                bf[ni][1] = __float_as_uint(Vs[(ks + tg + 4) * 68 + cc]);
            }
#pragma unroll
            for (int mi = 0; mi < 2; mi++)
#pragma unroll
                for (int ni = 0; ni < 2; ni++)
                    mma_tf32(acc[mi][ni], af[mi], bf[ni]);
        }
        __syncthreads();
    }

    // output (tf32-rounded: feeds Wo GEMM A operand)
#pragma unroll
    for (int mi = 0; mi < 2; mi++) {
        int rr = wr * 32 + mi * 16 + g;
        float i0v = 1.0f / rowl[rr];
        float i8v = 1.0f / rowl[rr + 8];
#pragma unroll
        for (int ni = 0; ni < 2; ni++) {
            int cc = wc * 16 + ni * 8 + tg * 2;
            float2 o0, o1;
            o0.x = rtf(acc[mi][ni][0] * i0v);
            o0.y = rtf(acc[mi][ni][1] * i0v);
            o1.x = rtf(acc[mi][ni][2] * i8v);
            o1.y = rtf(acc[mi][ni][3] * i8v);
            *(float2*)(out + ((size_t)(b * LSEQ + q0 + rr) * DMODEL) + h * HDIM + cc) = o0;
            *(float2*)(out + ((size_t)(b * LSEQ + q0 + rr + 8) * DMODEL) + h * HDIM + cc) = o1;
        }
    }
}

// ---------------- LayerNorm: one block per row (D=1024) --------------------
// Optional second output Yr = tf32-rounded copy (for downstream GEMM A).
__global__ __launch_bounds__(256) void ln_kernel(
    const float* __restrict__ X, const float* __restrict__ gam,
    const float* __restrict__ bet, float* __restrict__ Y, float* __restrict__ Yr) {
    __shared__ float red[8];
    __shared__ float sMean, sVar;
    const int row = blockIdx.x;
    const int tid = threadIdx.x;
    const float* x = X + (size_t)row * DMODEL;
    float4 v = *(const float4*)(x + tid * 4);
    float s = v.x + v.y + v.z + v.w;
#pragma unroll
    for (int o = 16; o; o >>= 1) s += __shfl_xor_sync(0xffffffffu, s, o);
    int w = tid >> 5, lane = tid & 31;
    if (lane == 0) red[w] = s;
    __syncthreads();
    if (tid == 0) {
        float t = 0;
#pragma unroll
        for (int i = 0; i < 8; i++) t += red[i];
        sMean = t * (1.0f / DMODEL);
    }
    __syncthreads();
    float m = sMean;
    float dx = v.x - m, dy = v.y - m, dz = v.z - m, dw = v.w - m;
    float q = dx * dx + dy * dy + dz * dz + dw * dw;
#pragma unroll
    for (int o = 16; o; o >>= 1) q += __shfl_xor_sync(0xffffffffu, q, o);
    if (lane == 0) red[w] = q;
    __syncthreads();
    if (tid == 0) {
        float t = 0;
#pragma unroll
        for (int i = 0; i < 8; i++) t += red[i];
        sVar = t * (1.0f / DMODEL);
    }
    __syncthreads();
    float inv = rsqrtf(sVar + LN_EPS);
    float4 gv = *(const float4*)(gam + tid * 4);
    float4 bv = *(const float4*)(bet + tid * 4);
    float4 o;
    o.x = dx * inv * gv.x + bv.x;
    o.y = dy * inv * gv.y + bv.y;
    o.z = dz * inv * gv.z + bv.z;
    o.w = dw * inv * gv.w + bv.w;
    *(float4*)(Y + (size_t)row * DMODEL + tid * 4) = o;
    if (Yr) {
        float4 r;
        r.x = rtf(o.x); r.y = rtf(o.y); r.z = rtf(o.z); r.w = rtf(o.w);
        *(float4*)(Yr + (size_t)row * DMODEL + tid * 4) = r;
    }
}

// ---------------- launch ----------------------------------------------------
extern "C" void kernel_launch(void* const* d_in, const int* in_sizes, int n_in,
                              void* d_out, int out_size) {
    const float* q  = (const float*)d_in[0];
    const float* kv = (const float*)d_in[1];
    const unsigned char* kvm = (const unsigned char*)d_in[2];
    const float* Wq = (const float*)d_in[3];
    const float* bq = (const float*)d_in[4];
    const float* Wk = (const float*)d_in[5];
    const float* bk = (const float*)d_in[6];
    const float* Wv = (const float*)d_in[7];
    const float* bv = (const float*)d_in[8];
    const float* Wo = (const float*)d_in[9];
    const float* bo = (const float*)d_in[10];
    const float* ln1g = (const float*)d_in[11];
    const float* ln1b = (const float*)d_in[12];
    const float* W1 = (const float*)d_in[13];
    const float* b1 = (const float*)d_in[14];
    const float* W2 = (const float*)d_in[15];
    const float* b2 = (const float*)d_in[16];
    const float* ln2g = (const float*)d_in[17];
    const float* ln2b = (const float*)d_in[18];
    float* out = (float*)d_out;

    float *qp, *kp, *vp, *att, *y, *x, *xr, *hbuf, *qr, *kvr;
    float *wqr, *wkr, *wvr, *wor, *w1r, *w2r;
    int *allpad, *mstride;
    unsigned char* emask;
    cudaGetSymbolAddress((void**)&qp, g_qp);
    cudaGetSymbolAddress((void**)&kp, g_kp);
    cudaGetSymbolAddress((void**)&vp, g_vp);
    cudaGetSymbolAddress((void**)&att, g_att);
    cudaGetSymbolAddress((void**)&y, g_y);
    cudaGetSymbolAddress((void**)&x, g_x);
    cudaGetSymbolAddress((void**)&xr, g_xr);
    cudaGetSymbolAddress((void**)&hbuf, g_h);
    cudaGetSymbolAddress((void**)&qr, g_qr);
    cudaGetSymbolAddress((void**)&kvr, g_kvr);
    cudaGetSymbolAddress((void**)&wqr, g_wqr);
    cudaGetSymbolAddress((void**)&wkr, g_wkr);
    cudaGetSymbolAddress((void**)&wvr, g_wvr);
    cudaGetSymbolAddress((void**)&wor, g_wor);
    cudaGetSymbolAddress((void**)&w1r, g_w1r);
    cudaGetSymbolAddress((void**)&w2r, g_w2r);
    cudaGetSymbolAddress((void**)&allpad, g_allpad);
    cudaGetSymbolAddress((void**)&emask, g_emask);
    cudaGetSymbolAddress((void**)&mstride, g_mstride);

    dim3 blk(256);
    dim3 gP(DMODEL / 128, MROWS / 128);     // (8, 64)
    dim3 gF1(DFF / 128, MROWS / 128);       // (32, 64)

    // mask normalization first
    detect_mask_stride<<<1, 256>>>(kvm, mstride);
    mask_prep<<<BATCH, 256>>>(kvm, mstride, emask, allpad);

    // pre-round GEMM operands to tf32 (hoists cvt out of GEMM mainloops)
    const int DD4 = DMODEL * DMODEL / 4;
    round_tf32<<<(MROWS * DMODEL / 4 + 255) / 256, 256>>>(q,  qr,  MROWS * DMODEL / 4);
    round_tf32<<<(MROWS * DMODEL / 4 + 255) / 256, 256>>>(kv, kvr, MROWS * DMODEL / 4);
    round_tf32<<<(DD4 + 255) / 256, 256>>>(Wq, wqr, DD4);
    round_tf32<<<(DD4 + 255) / 256, 256>>>(Wk, wkr, DD4);
    round_tf32<<<(DD4 + 255) / 256, 256>>>(Wv, wvr, DD4);
    round_tf32<<<(DD4 + 255) / 256, 256>>>(Wo, wor, DD4);
    round_tf32<<<(DMODEL * DFF / 4 + 255) / 256, 256>>>(W1, w1r, DMODEL * DFF / 4);
    round_tf32<<<(DMODEL * DFF / 4 + 255) / 256, 256>>>(W2, w2r, DMODEL * DFF / 4);

    // QKV projections (outputs tf32-rounded for the attention mma)
    sgemm_tc<<<gP, blk>>>(qr,  wqr, bq, nullptr, qp, MROWS, DMODEL, DMODEL, 0, 1);
    sgemm_tc<<<gP, blk>>>(kvr, wkr, bk, nullptr, kp, MROWS, DMODEL, DMODEL, 0, 1);
    sgemm_tc<<<gP, blk>>>(kvr, wvr, bv, nullptr, vp, MROWS, DMODEL, DMODEL, 0, 1);

    // attention (tensor-core)
    cudaFuncSetAttribute(attn_tc, cudaFuncAttributeMaxDynamicSharedMemorySize,
                         ATT_SMEM_BYTES);
    attn_tc<<<dim3(LSEQ / 64, NHEAD, BATCH), blk, ATT_SMEM_BYTES>>>(
        qp, kp, vp, emask, allpad, att);

    // O projection + residual (exact q), LN1 (exact + rounded copies)
    sgemm_tc<<<gP, blk>>>(att, wor, bo, q, y, MROWS, DMODEL, DMODEL, 0, 0);
    ln_kernel<<<MROWS, blk>>>(y, ln1g, ln1b, x, xr);

    // FFN
    sgemm_tc<<<gF1, blk>>>(xr, w1r, b1, nullptr, hbuf, MROWS, DFF, DMODEL, 1, 1);
    sgemm_tc<<<gP, blk>>>(hbuf, w2r, b2, x, y, MROWS, DMODEL, DFF, 0, 0);

    // LN2 -> output
    ln_kernel<<<MROWS, blk>>>(y, ln2g, ln2b, out, nullptr);
}

// round 6
// speedup vs baseline: 5.7373x; 2.3193x over previous
#include <cuda_runtime.h>
#include <cuda_fp16.h>
#include <stdint.h>
#include <math.h>

// Problem constants
#define BATCH 8
#define LSEQ 1024
#define DMODEL 1024
#define NHEAD 16
#define HDIM 64
#define DFF 4096
#define MROWS (BATCH * LSEQ)   // 8192
#define ATT_SCALE 0.125f
#define LN_EPS 1e-5f

// ---------------- scratch (device globals; no allocation allowed) ----------
__device__ __half g_qh[MROWS * DMODEL];
__device__ __half g_kvh[MROWS * DMODEL];
__device__ __half g_qph[MROWS * DMODEL];
__device__ __half g_kph[MROWS * DMODEL];
__device__ __half g_vph[MROWS * DMODEL];
__device__ __half g_atth[MROWS * DMODEL];
__device__ __half g_xh[MROWS * DMODEL];
__device__ __half g_hh[(size_t)MROWS * DFF];
__device__ __half g_wqt[DMODEL * DMODEL];   // transposed weights [N][K] half
__device__ __half g_wkt[DMODEL * DMODEL];
__device__ __half g_wvt[DMODEL * DMODEL];
__device__ __half g_wot[DMODEL * DMODEL];
__device__ __half g_w1t[DMODEL * DFF];      // [4096][1024]
__device__ __half g_w2t[DFF * DMODEL];      // [1024][4096]
__device__ float g_y[MROWS * DMODEL];
__device__ float g_x[MROWS * DMODEL];
__device__ int g_allpad[BATCH];
__device__ unsigned char g_emask[BATCH * LSEQ];
__device__ int g_mstride[1];

// ---------------- helpers ----------------------------------------------------
__device__ __forceinline__ void cpa16(uint32_t s, const void* g) {
    asm volatile("cp.async.cg.shared.global [%0], [%1], 16;\n" :: "r"(s), "l"(g));
}
__device__ __forceinline__ void ldmat_x4(uint32_t* r, uint32_t addr) {
    asm volatile("ldmatrix.sync.aligned.m8n8.x4.shared.b16 {%0,%1,%2,%3}, [%4];"
        : "=r"(r[0]), "=r"(r[1]), "=r"(r[2]), "=r"(r[3]) : "r"(addr));
}
__device__ __forceinline__ void ldmat_x4t(uint32_t* r, uint32_t addr) {
    asm volatile("ldmatrix.sync.aligned.m8n8.x4.trans.shared.b16 {%0,%1,%2,%3}, [%4];"
        : "=r"(r[0]), "=r"(r[1]), "=r"(r[2]), "=r"(r[3]) : "r"(addr));
}
__device__ __forceinline__ void mma_f16(float* c, const uint32_t* a, const uint32_t* b) {
    asm volatile(
        "mma.sync.aligned.m16n8k16.row.col.f32.f16.f16.f32 "
        "{%0,%1,%2,%3}, {%4,%5,%6,%7}, {%8,%9}, {%0,%1,%2,%3};"
        : "+f"(c[0]), "+f"(c[1]), "+f"(c[2]), "+f"(c[3])
        : "r"(a[0]), "r"(a[1]), "r"(a[2]), "r"(a[3]), "r"(b[0]), "r"(b[1]));
}

// ---------------- FP16 tensor-core GEMM -------------------------------------
// C[M,N] = A[M,K] @ Bt[N,K]^T + bias (+relu) (+res). A,Bt are half (K-major).
// Outputs: C fp32 (optional), Ch half (optional).
// 128x128 block, BK=32 halves, 256 thr (8 warps 2x4, warp tile 64x32),
// cp.async double-buffered; smem stride 40 halves (conflict-free for ldmatrix).
#define GST 40
#define GSTAGE_B (128 * GST * 2)   // 10240 bytes per stage per operand

__device__ __forceinline__ void hfill(const __half* __restrict__ A,
                                      const __half* __restrict__ Bt, int K,
                                      int rowBlk, int colBlk, int kt,
                                      uint32_t abase, uint32_t bbase, int tid) {
#pragma unroll
    for (int c = tid; c < 512; c += 256) {
        int row = c >> 2, ch = c & 3;
        cpa16(abase + row * (GST * 2) + ch * 16,
              A + (size_t)(rowBlk + row) * K + kt * 32 + ch * 8);
        cpa16(bbase + row * (GST * 2) + ch * 16,
              Bt + (size_t)(colBlk + row) * K + kt * 32 + ch * 8);
    }
}

__global__ __launch_bounds__(256, 2) void hgemm(
    const __half* __restrict__ A, const __half* __restrict__ Bt,
    const float* __restrict__ bias, const float* __restrict__ res,
    float* __restrict__ C, __half* __restrict__ Ch,
    int M, int N, int K, int doRelu) {
    __shared__ __align__(16) __half As[2][128 * GST];
    __shared__ __align__(16) __half Bs[2][128 * GST];

    const int tid = threadIdx.x;
    const int lane = tid & 31, warp = tid >> 5;
    const int wr = warp & 1, wc = warp >> 1;
    const int g = lane >> 2, tg = lane & 3;
    const int grp = lane >> 3, r8 = lane & 7;
    const int rowBlk = blockIdx.y * 128, colBlk = blockIdx.x * 128;

    uint32_t asb = (uint32_t)__cvta_generic_to_shared(&As[0][0]);
    uint32_t bsb = (uint32_t)__cvta_generic_to_shared(&Bs[0][0]);

    float acc[4][4][4];
#pragma unroll
    for (int i = 0; i < 4; i++)
#pragma unroll
        for (int j = 0; j < 4; j++)
#pragma unroll
            for (int v = 0; v < 4; v++) acc[i][j][v] = 0.f;

    const int nk = K / 32;

    hfill(A, Bt, K, rowBlk, colBlk, 0, asb, bsb, tid);
    asm volatile("cp.async.commit_group;");

    for (int kt = 0; kt < nk; kt++) {
        if (kt + 1 < nk) {
            int s2 = (kt + 1) & 1;
            hfill(A, Bt, K, rowBlk, colBlk, kt + 1,
                  asb + s2 * GSTAGE_B, bsb + s2 * GSTAGE_B, tid);
            asm volatile("cp.async.commit_group;");
            asm volatile("cp.async.wait_group 1;");
        } else {
            asm volatile("cp.async.wait_group 0;");
        }
        __syncthreads();
        const uint32_t ab = asb + (kt & 1) * GSTAGE_B;
        const uint32_t bb = bsb + (kt & 1) * GSTAGE_B;
#pragma unroll
        for (int ks = 0; ks < 32; ks += 16) {
            uint32_t af[4][4], bf[2][4];
#pragma unroll
            for (int mi = 0; mi < 4; mi++) {
                int row = wr * 64 + mi * 16 + r8 + (grp & 1) * 8;
                int kk = ks + (grp >> 1) * 8;
                ldmat_x4(af[mi], ab + row * (GST * 2) + kk * 2);
            }
#pragma unroll
            for (int np = 0; np < 2; np++) {
                int n = wc * 32 + np * 16 + r8 + (grp >> 1) * 8;
                int kk = ks + (grp & 1) * 8;
                ldmat_x4(bf[np], bb + n * (GST * 2) + kk * 2);
            }
#pragma unroll
            for (int mi = 0; mi < 4; mi++)
#pragma unroll
                for (int ni = 0; ni < 4; ni++) {
                    uint32_t bq[2] = {bf[ni >> 1][(ni & 1) * 2],
                                      bf[ni >> 1][(ni & 1) * 2 + 1]};
                    mma_f16(acc[mi][ni], af[mi], bq);
                }
        }
        __syncthreads();
    }

    // epilogue: c0,c1 -> (row g, col 2tg..2tg+1), c2,c3 -> (row g+8)
#pragma unroll
    for (int mi = 0; mi < 4; mi++) {
#pragma unroll
        for (int ni = 0; ni < 4; ni++) {
            int r0 = rowBlk + wr * 64 + mi * 16 + g;
            int c = colBlk + wc * 32 + ni * 8 + tg * 2;
            float2 bb = *(const float2*)(bias + c);
            float2 o0, o1;
            o0.x = acc[mi][ni][0] + bb.x;
            o0.y = acc[mi][ni][1] + bb.y;
            o1.x = acc[mi][ni][2] + bb.x;
            o1.y = acc[mi][ni][3] + bb.y;
            if (doRelu) {
                o0.x = fmaxf(o0.x, 0.f); o0.y = fmaxf(o0.y, 0.f);
                o1.x = fmaxf(o1.x, 0.f); o1.y = fmaxf(o1.y, 0.f);
            }
            if (res) {
                float2 r0v = *(const float2*)(res + (size_t)r0 * N + c);
                float2 r1v = *(const float2*)(res + (size_t)(r0 + 8) * N + c);
                o0.x += r0v.x; o0.y += r0v.y;
                o1.x += r1v.x; o1.y += r1v.y;
            }
            if (C) {
                *(float2*)(C + (size_t)r0 * N + c) = o0;
                *(float2*)(C + (size_t)(r0 + 8) * N + c) = o1;
            }
            if (Ch) {
                *(__half2*)(Ch + (size_t)r0 * N + c) = __floats2half2_rn(o0.x, o0.y);
                *(__half2*)(Ch + (size_t)(r0 + 8) * N + c) = __floats2half2_rn(o1.x, o1.y);
            }
        }
    }
}

// ---------------- conversions ------------------------------------------------
__global__ __launch_bounds__(256) void f32_to_f16(const float* __restrict__ in,
                                                  __half* __restrict__ out, int n4) {
    int i = blockIdx.x * 256 + threadIdx.x;
    if (i < n4) {
        float4 v = ((const float4*)in)[i];
        ((__half2*)out)[i * 2]     = __floats2half2_rn(v.x, v.y);
        ((__half2*)out)[i * 2 + 1] = __floats2half2_rn(v.z, v.w);
    }
}

// out[n][k] = half(in[k][n]); in is [R rows(K), C cols(N)]
__global__ __launch_bounds__(256) void transpose_h(const float* __restrict__ in,
                                                   __half* __restrict__ out,
                                                   int R, int Ccols) {
    __shared__ float t[32][33];
    int c = blockIdx.x * 32 + threadIdx.x;
    int r0 = blockIdx.y * 32 + threadIdx.y;
#pragma unroll
    for (int i = 0; i < 32; i += 8)
        t[threadIdx.y + i][threadIdx.x] = in[(size_t)(r0 + i) * Ccols + c];
    __syncthreads();
    int oc = blockIdx.y * 32 + threadIdx.x;
    int orr = blockIdx.x * 32 + threadIdx.y;
#pragma unroll
    for (int i = 0; i < 32; i += 8)
        out[(size_t)(orr + i) * R + oc] = __float2half_rn(t[threadIdx.x][threadIdx.y + i]);
}

// ---------------- mask dtype detection + normalization ---------------------
__global__ void detect_mask_stride(const unsigned char* __restrict__ m, int* stride_out) {
    __shared__ int any;
    if (threadIdx.x == 0) any = 0;
    __syncthreads();
    int a = 0;
    for (int j = threadIdx.x; j < 2048; j += 256) a |= m[j * 4 + 1];
    if (a) atomicOr(&any, 1);
    __syncthreads();
    if (threadIdx.x == 0) *stride_out = any ? 1 : 4;
}

__global__ void mask_prep(const unsigned char* __restrict__ m,
                          const int* __restrict__ stridep,
                          unsigned char* __restrict__ em, int* __restrict__ allpad) {
    int b = blockIdx.x;
    int st = *stridep;
    int ok = 1;
    for (int j = threadIdx.x; j < LSEQ; j += 256) {
        unsigned char v = (m[(size_t)(b * LSEQ + j) * st] != 0) ? 1 : 0;
        em[b * LSEQ + j] = v;
        ok &= (int)v;
    }
    ok = __syncthreads_and(ok);
    if (threadIdx.x == 0) allpad[b] = ok;
}

// ---------------- FP16 tensor-core flash attention --------------------------
// Qs/Ks [row][d] stride 72 halves; Vs [j][d] (read via ldmatrix.trans);
// Ph [i][j] half (PV A-frag); Ps fp32 scores for softmax.
#define AST 72
#define ATTH_SMEM (4 * 64 * AST * 2 + 64 * 68 * 4 + 4 * 64 * 4)   // 55296

__global__ __launch_bounds__(256) void attn_h(
    const __half* __restrict__ qp, const __half* __restrict__ kp,
    const __half* __restrict__ vp, const unsigned char* __restrict__ em,
    const int* __restrict__ allpad, __half* __restrict__ out) {
    extern __shared__ char smraw[];
    __half* Qs = (__half*)smraw;
    __half* Ks = Qs + 64 * AST;
    __half* Vs = Ks + 64 * AST;
    __half* Ph = Vs + 64 * AST;
    float* Ps = (float*)(Ph + 64 * AST);
    float* rowm = Ps + 64 * 68;
    float* rowl = rowm + 64;
    float* rowa = rowl + 64;
    float* mk = rowa + 64;
    const uint32_t sb = (uint32_t)__cvta_generic_to_shared(smraw);
    const uint32_t qsb = sb, ksb = sb + 64 * AST * 2,
                   vsb = sb + 2 * 64 * AST * 2, phb = sb + 3 * 64 * AST * 2;

    const int b = blockIdx.z, h = blockIdx.y, q0 = blockIdx.x * 64;
    const int tid = threadIdx.x;
    const int lane = tid & 31, warp = tid >> 5;
    const int g = lane >> 2, tg = lane & 3;
    const int grp = lane >> 3, r8 = lane & 7;
    const int wr = warp & 1, wc = warp >> 1;   // warp tile 32(m) x 16(n)
    const int ap = allpad[b];
    const size_t qoff = ((size_t)(b * LSEQ + q0) * DMODEL) + h * HDIM;

    for (int t = tid; t < 512; t += 256) {
        int i = t >> 3, ch = t & 7;
        *(uint4*)&Qs[i * AST + ch * 8] =
            *(const uint4*)(qp + qoff + (size_t)i * DMODEL + ch * 8);
    }
    if (tid < 64) { rowm[tid] = -1e30f; rowl[tid] = 0.f; }

    float acc[2][2][4];
#pragma unroll
    for (int mi = 0; mi < 2; mi++)
#pragma unroll
        for (int ni = 0; ni < 2; ni++)
#pragma unroll
            for (int v = 0; v < 4; v++) acc[mi][ni][v] = 0.f;

    for (int kt = 0; kt < 16; kt++) {
        const size_t koff = ((size_t)(b * LSEQ + kt * 64) * DMODEL) + h * HDIM;
        for (int t = tid; t < 512; t += 256) {
            int j = t >> 3, ch = t & 7;
            *(uint4*)&Ks[j * AST + ch * 8] =
                *(const uint4*)(kp + koff + (size_t)j * DMODEL + ch * 8);
            *(uint4*)&Vs[j * AST + ch * 8] =
                *(const uint4*)(vp + koff + (size_t)j * DMODEL + ch * 8);
        }
        if (tid < 64) {
            int kidx = kt * 64 + tid;
            int msk = em[b * LSEQ + kidx];
            if (ap && kidx == LSEQ - 1) msk = 0;
            mk[tid] = msk ? 1.0f : 0.0f;
        }
        __syncthreads();

        // ---- S = Q K^T ----
        float s[2][2][4];
#pragma unroll
        for (int mi = 0; mi < 2; mi++)
#pragma unroll
            for (int ni = 0; ni < 2; ni++)
#pragma unroll
                for (int v = 0; v < 4; v++) s[mi][ni][v] = 0.f;
#pragma unroll
        for (int ks = 0; ks < 64; ks += 16) {
            uint32_t af[2][4], bf[4];
#pragma unroll
            for (int mi = 0; mi < 2; mi++) {
                int row = wr * 32 + mi * 16 + r8 + (grp & 1) * 8;
                ldmat_x4(af[mi], qsb + (row * AST + ks + (grp >> 1) * 8) * 2);
            }
            {
                int n = wc * 16 + r8 + (grp >> 1) * 8;
                ldmat_x4(bf, ksb + (n * AST + ks + (grp & 1) * 8) * 2);
            }
#pragma unroll
            for (int mi = 0; mi < 2; mi++)
#pragma unroll
                for (int ni = 0; ni < 2; ni++) {
                    uint32_t bq[2] = {bf[ni * 2], bf[ni * 2 + 1]};
                    mma_f16(s[mi][ni], af[mi], bq);
                }
        }
        // scatter scale+mask into Ps (fp32)
#pragma unroll
        for (int mi = 0; mi < 2; mi++) {
            int rr = wr * 32 + mi * 16 + g;
#pragma unroll
            for (int ni = 0; ni < 2; ni++) {
                int cc = wc * 16 + ni * 8 + tg * 2;
                float m0 = mk[cc], m1 = mk[cc + 1];
                Ps[rr * 68 + cc]           = (m0 != 0.f) ? -10000.f : s[mi][ni][0] * ATT_SCALE;
                Ps[rr * 68 + cc + 1]       = (m1 != 0.f) ? -10000.f : s[mi][ni][1] * ATT_SCALE;
                Ps[(rr + 8) * 68 + cc]     = (m0 != 0.f) ? -10000.f : s[mi][ni][2] * ATT_SCALE;
                Ps[(rr + 8) * 68 + cc + 1] = (m1 != 0.f) ? -10000.f : s[mi][ni][3] * ATT_SCALE;
            }
        }
        __syncthreads();

        // ---- online softmax (fp32), write P as half to Ph ----
        {
            int row = tid >> 2, sub = tid & 3;
            int base = row * 68 + sub * 16;
            float4 p0 = *(float4*)&Ps[base];
            float4 p1 = *(float4*)&Ps[base + 4];
            float4 p2 = *(float4*)&Ps[base + 8];
            float4 p3 = *(float4*)&Ps[base + 12];
            float tm = fmaxf(fmaxf(fmaxf(p0.x, p0.y), fmaxf(p0.z, p0.w)),
                             fmaxf(fmaxf(p1.x, p1.y), fmaxf(p1.z, p1.w)));
            tm = fmaxf(tm, fmaxf(fmaxf(fmaxf(p2.x, p2.y), fmaxf(p2.z, p2.w)),
                                 fmaxf(fmaxf(p3.x, p3.y), fmaxf(p3.z, p3.w))));
            tm = fmaxf(tm, __shfl_xor_sync(0xffffffffu, tm, 1));
            tm = fmaxf(tm, __shfl_xor_sync(0xffffffffu, tm, 2));
            float m_old = rowm[row];
            float newm = fmaxf(m_old, tm);
            p0.x = __expf(p0.x - newm); p0.y = __expf(p0.y - newm);
            p0.z = __expf(p0.z - newm); p0.w = __expf(p0.w - newm);
            p1.x = __expf(p1.x - newm); p1.y = __expf(p1.y - newm);
            p1.z = __expf(p1.z - newm); p1.w = __expf(p1.w - newm);
            p2.x = __expf(p2.x - newm); p2.y = __expf(p2.y - newm);
            p2.z = __expf(p2.z - newm); p2.w = __expf(p2.w - newm);
            p3.x = __expf(p3.x - newm); p3.y = __expf(p3.y - newm);
            p3.z = __expf(p3.z - newm); p3.w = __expf(p3.w - newm);
            __half2 h0 = __floats2half2_rn(p0.x, p0.y);
            __half2 h1 = __floats2half2_rn(p0.z, p0.w);
            __half2 h2 = __floats2half2_rn(p1.x, p1.y);
            __half2 h3 = __floats2half2_rn(p1.z, p1.w);
            __half2 h4 = __floats2half2_rn(p2.x, p2.y);
            __half2 h5 = __floats2half2_rn(p2.z, p2.w);
            __half2 h6 = __floats2half2_rn(p3.x, p3.y);
            __half2 h7 = __floats2half2_rn(p3.z, p3.w);
            __half2* ph = (__half2*)&Ph[row * AST + sub * 16];
            ph[0] = h0; ph[1] = h1; ph[2] = h2; ph[3] = h3;
            ph[4] = h4; ph[5] = h5; ph[6] = h6; ph[7] = h7;
            // sum uses the half-rounded values so normalization matches PV input
            float sum = __low2float(h0) + __high2float(h0) + __low2float(h1) + __high2float(h1) +
                        __low2float(h2) + __high2float(h2) + __low2float(h3) + __high2float(h3) +
                        __low2float(h4) + __high2float(h4) + __low2float(h5) + __high2float(h5) +
                        __low2float(h6) + __high2float(h6) + __low2float(h7) + __high2float(h7);
            sum += __shfl_xor_sync(0xffffffffu, sum, 1);
            sum += __shfl_xor_sync(0xffffffffu, sum, 2);
            if (sub == 0) {
                float a = __expf(m_old - newm);
                rowa[row] = a;
                rowl[row] = rowl[row] * a + sum;
                rowm[row] = newm;
            }
        }
        __syncthreads();

        // ---- O = O*alpha + P @ V ----
#pragma unroll
        for (int mi = 0; mi < 2; mi++) {
            int rr = wr * 32 + mi * 16 + g;
            float a0 = rowa[rr], a8 = rowa[rr + 8];
#pragma unroll
            for (int ni = 0; ni < 2; ni++) {
                acc[mi][ni][0] *= a0; acc[mi][ni][1] *= a0;
                acc[mi][ni][2] *= a8; acc[mi][ni][3] *= a8;
            }
        }
#pragma unroll
        for (int ks = 0; ks < 64; ks += 16) {
            uint32_t af[2][4], bf[4];
#pragma unroll
            for (int mi = 0; mi < 2; mi++) {
                int row = wr * 32 + mi * 16 + r8 + (grp & 1) * 8;
                ldmat_x4(af[mi], phb + (row * AST + ks + (grp >> 1) * 8) * 2);
            }
            {
                int j = ks + r8 + (grp & 1) * 8;
                int d = wc * 16 + (grp >> 1) * 8;
                ldmat_x4t(bf, vsb + (j * AST + d) * 2);
            }
#pragma unroll
            for (int mi = 0; mi < 2; mi++)
#pragma unroll
                for (int ni = 0; ni < 2; ni++) {
                    uint32_t bq[2] = {bf[ni * 2], bf[ni * 2 + 1]};
                    mma_f16(acc[mi][ni], af[mi], bq);
                }
        }
        __syncthreads();
    }

    // output: half (feeds Wo GEMM A operand)
#pragma unroll
    for (int mi = 0; mi < 2; mi++) {
        int rr = wr * 32 + mi * 16 + g;
        float i0v = 1.0f / rowl[rr];
        float i8v = 1.0f / rowl[rr + 8];
#pragma unroll
        for (int ni = 0; ni < 2; ni++) {
            int cc = wc * 16 + ni * 8 + tg * 2;
            *(__half2*)(out + ((size_t)(b * LSEQ + q0 + rr) * DMODEL) + h * HDIM + cc) =
                __floats2half2_rn(acc[mi][ni][0] * i0v, acc[mi][ni][1] * i0v);
            *(__half2*)(out + ((size_t)(b * LSEQ + q0 + rr + 8) * DMODEL) + h * HDIM + cc) =
                __floats2half2_rn(acc[mi][ni][2] * i8v, acc[mi][ni][3] * i8v);
        }
    }
}

// ---------------- LayerNorm (optional half twin output) --------------------
__global__ __launch_bounds__(256) void ln_kernel(
    const float* __restrict__ X, const float* __restrict__ gam,
    const float* __restrict__ bet, float* __restrict__ Y, __half* __restrict__ Yh) {
    __shared__ float red[8];
    __shared__ float sMean, sVar;
    const int row = blockIdx.x;
    const int tid = threadIdx.x;
    const float* x = X + (size_t)row * DMODEL;
    float4 v = *(const float4*)(x + tid * 4);
    float s = v.x + v.y + v.z + v.w;
#pragma unroll
    for (int o = 16; o; o >>= 1) s += __shfl_xor_sync(0xffffffffu, s, o);
    int w = tid >> 5, lane = tid & 31;
    if (lane == 0) red[w] = s;
    __syncthreads();
    if (tid == 0) {
        float t = 0;
#pragma unroll
        for (int i = 0; i < 8; i++) t += red[i];
        sMean = t * (1.0f / DMODEL);
    }
    __syncthreads();
    float m = sMean;
    float dx = v.x - m, dy = v.y - m, dz = v.z - m, dw = v.w - m;
    float q = dx * dx + dy * dy + dz * dz + dw * dw;
#pragma unroll
    for (int o = 16; o; o >>= 1) q += __shfl_xor_sync(0xffffffffu, q, o);
    if (lane == 0) red[w] = q;
    __syncthreads();
    if (tid == 0) {
        float t = 0;
#pragma unroll
        for (int i = 0; i < 8; i++) t += red[i];
        sVar = t * (1.0f / DMODEL);
    }
    __syncthreads();
    float inv = rsqrtf(sVar + LN_EPS);
    float4 gv = *(const float4*)(gam + tid * 4);
    float4 bv = *(const float4*)(bet + tid * 4);
    float4 o;
    o.x = dx * inv * gv.x + bv.x;
    o.y = dy * inv * gv.y + bv.y;
    o.z = dz * inv * gv.z + bv.z;
    o.w = dw * inv * gv.w + bv.w;
    *(float4*)(Y + (size_t)row * DMODEL + tid * 4) = o;
    if (Yh) {
        __half2* yh = (__half2*)(Yh + (size_t)row * DMODEL + tid * 4);
        yh[0] = __floats2half2_rn(o.x, o.y);
        yh[1] = __floats2half2_rn(o.z, o.w);
    }
}

// ---------------- launch ----------------------------------------------------
extern "C" void kernel_launch(void* const* d_in, const int* in_sizes, int n_in,
                              void* d_out, int out_size) {
    const float* q  = (const float*)d_in[0];
    const float* kv = (const float*)d_in[1];
    const unsigned char* kvm = (const unsigned char*)d_in[2];
    const float* Wq = (const float*)d_in[3];
    const float* bq = (const float*)d_in[4];
    const float* Wk = (const float*)d_in[5];
    const float* bk = (const float*)d_in[6];
    const float* Wv = (const float*)d_in[7];
    const float* bv = (const float*)d_in[8];
    const float* Wo = (const float*)d_in[9];
    const float* bo = (const float*)d_in[10];
    const float* ln1g = (const float*)d_in[11];
    const float* ln1b = (const float*)d_in[12];
    const float* W1 = (const float*)d_in[13];
    const float* b1 = (const float*)d_in[14];
    const float* W2 = (const float*)d_in[15];
    const float* b2 = (const float*)d_in[16];
    const float* ln2g = (const float*)d_in[17];
    const float* ln2b = (const float*)d_in[18];
    float* out = (float*)d_out;

    __half *qh, *kvh, *qph, *kph, *vph, *atth, *xh, *hh;
    __half *wqt, *wkt, *wvt, *wot, *w1t, *w2t;
    float *y, *x;
    int *allpad, *mstride;
    unsigned char* emask;
    cudaGetSymbolAddress((void**)&qh, g_qh);
    cudaGetSymbolAddress((void**)&kvh, g_kvh);
    cudaGetSymbolAddress((void**)&qph, g_qph);
    cudaGetSymbolAddress((void**)&kph, g_kph);
    cudaGetSymbolAddress((void**)&vph, g_vph);
    cudaGetSymbolAddress((void**)&atth, g_atth);
    cudaGetSymbolAddress((void**)&xh, g_xh);
    cudaGetSymbolAddress((void**)&hh, g_hh);
    cudaGetSymbolAddress((void**)&wqt, g_wqt);
    cudaGetSymbolAddress((void**)&wkt, g_wkt);
    cudaGetSymbolAddress((void**)&wvt, g_wvt);
    cudaGetSymbolAddress((void**)&wot, g_wot);
    cudaGetSymbolAddress((void**)&w1t, g_w1t);
    cudaGetSymbolAddress((void**)&w2t, g_w2t);
    cudaGetSymbolAddress((void**)&y, g_y);
    cudaGetSymbolAddress((void**)&x, g_x);
    cudaGetSymbolAddress((void**)&allpad, g_allpad);
    cudaGetSymbolAddress((void**)&emask, g_emask);
    cudaGetSymbolAddress((void**)&mstride, g_mstride);

    cudaFuncSetAttribute(attn_h, cudaFuncAttributeMaxDynamicSharedMemorySize, ATTH_SMEM);

    dim3 blk(256);
    dim3 t32(32, 8);
    dim3 gP(DMODEL / 128, MROWS / 128);     // (8, 64)
    dim3 gF1(DFF / 128, MROWS / 128);       // (32, 64)

    // mask normalization
    detect_mask_stride<<<1, 256>>>(kvm, mstride);
    mask_prep<<<BATCH, 256>>>(kvm, mstride, emask, allpad);

    // operand prep: activations -> half; weights -> transposed half [N][K]
    f32_to_f16<<<(MROWS * DMODEL / 4 + 255) / 256, 256>>>(q,  qh,  MROWS * DMODEL / 4);
    f32_to_f16<<<(MROWS * DMODEL / 4 + 255) / 256, 256>>>(kv, kvh, MROWS * DMODEL / 4);
    transpose_h<<<dim3(32, 32), t32>>>(Wq, wqt, DMODEL, DMODEL);
    transpose_h<<<dim3(32, 32), t32>>>(Wk, wkt, DMODEL, DMODEL);
    transpose_h<<<dim3(32, 32), t32>>>(Wv, wvt, DMODEL, DMODEL);
    transpose_h<<<dim3(32, 32), t32>>>(Wo, wot, DMODEL, DMODEL);
    transpose_h<<<dim3(128, 32), t32>>>(W1, w1t, DMODEL, DFF);
    transpose_h<<<dim3(32, 128), t32>>>(W2, w2t, DFF, DMODEL);

    // QKV projections (half outputs only)
    hgemm<<<gP, blk>>>(qh,  wqt, bq, nullptr, nullptr, qph, MROWS, DMODEL, DMODEL, 0);
    hgemm<<<gP, blk>>>(kvh, wkt, bk, nullptr, nullptr, kph, MROWS, DMODEL, DMODEL, 0);
    hgemm<<<gP, blk>>>(kvh, wvt, bv, nullptr, nullptr, vph, MROWS, DMODEL, DMODEL, 0);

    // attention
    attn_h<<<dim3(LSEQ / 64, NHEAD, BATCH), blk, ATTH_SMEM>>>(
        qph, kph, vph, emask, allpad, atth);

    // O projection + residual (fp32 q), LN1 (fp32 + half twin)
    hgemm<<<gP, blk>>>(atth, wot, bo, q, y, nullptr, MROWS, DMODEL, DMODEL, 0);
    ln_kernel<<<MROWS, blk>>>(y, ln1g, ln1b, x, xh);

    // FFN
    hgemm<<<gF1, blk>>>(xh, w1t, b1, nullptr, nullptr, hh, MROWS, DFF, DMODEL, 1);
    hgemm<<<gP, blk>>>(hh, w2t, b2, x, y, nullptr, MROWS, DMODEL, DFF, 0);

    // LN2 -> output
    ln_kernel<<<MROWS, blk>>>(y, ln2g, ln2b, out, nullptr);
}

// round 7
// speedup vs baseline: 5.9237x; 1.0325x over previous
#include <cuda_runtime.h>
#include <cuda_fp16.h>
#include <stdint.h>
#include <math.h>

// Problem constants
#define BATCH 8
#define LSEQ 1024
#define DMODEL 1024
#define NHEAD 16
#define HDIM 64
#define DFF 4096
#define MROWS (BATCH * LSEQ)   // 8192
#define ATT_SCALE 0.125f
#define LN_EPS 1e-5f

// ---------------- scratch (device globals; no allocation allowed) ----------
__device__ __half g_qh[MROWS * DMODEL];
__device__ __half g_kvh[MROWS * DMODEL];
__device__ __half g_qph[MROWS * DMODEL];
__device__ __half g_kvph[(size_t)MROWS * 2 * DMODEL];   // packed [row][K|V]
__device__ __half g_atth[MROWS * DMODEL];
__device__ __half g_xh[MROWS * DMODEL];
__device__ __half g_hh[(size_t)MROWS * DFF];
__device__ __half g_wqt[DMODEL * DMODEL];               // [N][K] half
__device__ __half g_wkvt[2 * DMODEL * DMODEL];          // packed Wk^T|Wv^T
__device__ __half g_wot[DMODEL * DMODEL];
__device__ __half g_w1t[DMODEL * DFF];
__device__ __half g_w2t[DFF * DMODEL];
__device__ float g_bkv[2 * DMODEL];
__device__ float g_y[MROWS * DMODEL];
__device__ float g_x[MROWS * DMODEL];
__device__ int g_allpad[BATCH];
__device__ unsigned char g_emask[BATCH * LSEQ];
__device__ int g_mstride[1];

// ---------------- helpers ----------------------------------------------------
__device__ __forceinline__ void cpa16(uint32_t s, const void* g) {
    asm volatile("cp.async.cg.shared.global [%0], [%1], 16;\n" :: "r"(s), "l"(g));
}
__device__ __forceinline__ void ldmat_x4(uint32_t* r, uint32_t addr) {
    asm volatile("ldmatrix.sync.aligned.m8n8.x4.shared.b16 {%0,%1,%2,%3}, [%4];"
        : "=r"(r[0]), "=r"(r[1]), "=r"(r[2]), "=r"(r[3]) : "r"(addr));
}
__device__ __forceinline__ void ldmat_x4t(uint32_t* r, uint32_t addr) {
    asm volatile("ldmatrix.sync.aligned.m8n8.x4.trans.shared.b16 {%0,%1,%2,%3}, [%4];"
        : "=r"(r[0]), "=r"(r[1]), "=r"(r[2]), "=r"(r[3]) : "r"(addr));
}
__device__ __forceinline__ void mma_f16(float* c, const uint32_t* a, const uint32_t* b) {
    asm volatile(
        "mma.sync.aligned.m16n8k16.row.col.f32.f16.f16.f32 "
        "{%0,%1,%2,%3}, {%4,%5,%6,%7}, {%8,%9}, {%0,%1,%2,%3};"
        : "+f"(c[0]), "+f"(c[1]), "+f"(c[2]), "+f"(c[3])
        : "r"(a[0]), "r"(a[1]), "r"(a[2]), "r"(a[3]), "r"(b[0]), "r"(b[1]));
}

// ---------------- FP16 tensor-core GEMM (128x256 tile, BK=64) ---------------
// C[M,N] = A[M,K] @ Bt[N,K]^T + bias (+relu) (+res). A,Bt half (K-major).
// 256 threads (8 warps 2x4), warp tile 64x64. 2-stage cp.async, dyn smem.
#define GST 72                          // halves; stride 144B, conflict-free
#define A_STAGE (128 * GST * 2)         // 18432 B
#define B_STAGE (256 * GST * 2)         // 36864 B
#define HG_SMEM (2 * (A_STAGE + B_STAGE))  // 110592 B

__device__ __forceinline__ void hfill(const __half* __restrict__ A,
                                      const __half* __restrict__ Bt, int K,
                                      int rowBlk, int colBlk, int kt,
                                      uint32_t abase, uint32_t bbase, int tid) {
#pragma unroll
    for (int c = tid; c < 1024; c += 256) {
        int row = c >> 3, ch = c & 7;
        cpa16(abase + row * (GST * 2) + ch * 16,
              A + (size_t)(rowBlk + row) * K + kt * 64 + ch * 8);
    }
#pragma unroll
    for (int c = tid; c < 2048; c += 256) {
        int row = c >> 3, ch = c & 7;
        cpa16(bbase + row * (GST * 2) + ch * 16,
              Bt + (size_t)(colBlk + row) * K + kt * 64 + ch * 8);
    }
}

__global__ __launch_bounds__(256, 1) void hgemm(
    const __half* __restrict__ A, const __half* __restrict__ Bt,
    const float* __restrict__ bias, const float* __restrict__ res,
    float* __restrict__ C, __half* __restrict__ Ch,
    int M, int N, int K, int doRelu) {
    extern __shared__ char smraw[];
    const uint32_t sb = (uint32_t)__cvta_generic_to_shared(smraw);
    const uint32_t asb = sb;                     // A stages back-to-back
    const uint32_t bsb = sb + 2 * A_STAGE;       // B stages

    const int tid = threadIdx.x;
    const int lane = tid & 31, warp = tid >> 5;
    const int wr = warp & 1, wc = warp >> 1;     // warp tile: (wr*64, wc*64)
    const int g = lane >> 2, tg = lane & 3;
    const int grp = lane >> 3, r8 = lane & 7;
    const int rowBlk = blockIdx.y * 128, colBlk = blockIdx.x * 256;

    float acc[4][8][4];
#pragma unroll
    for (int i = 0; i < 4; i++)
#pragma unroll
        for (int j = 0; j < 8; j++)
#pragma unroll
            for (int v = 0; v < 4; v++) acc[i][j][v] = 0.f;

    const int nk = K / 64;

    hfill(A, Bt, K, rowBlk, colBlk, 0, asb, bsb, tid);
    asm volatile("cp.async.commit_group;");

    for (int kt = 0; kt < nk; kt++) {
        if (kt + 1 < nk) {
            int s2 = (kt + 1) & 1;
            hfill(A, Bt, K, rowBlk, colBlk, kt + 1,
                  asb + s2 * A_STAGE, bsb + s2 * B_STAGE, tid);
            asm volatile("cp.async.commit_group;");
            asm volatile("cp.async.wait_group 1;");
        } else {
            asm volatile("cp.async.wait_group 0;");
        }
        __syncthreads();
        const uint32_t ab = asb + (kt & 1) * A_STAGE;
        const uint32_t bb = bsb + (kt & 1) * B_STAGE;
#pragma unroll
        for (int ks = 0; ks < 64; ks += 16) {
            uint32_t af[4][4], bf[4][4];
#pragma unroll
            for (int mi = 0; mi < 4; mi++) {
                int row = wr * 64 + mi * 16 + r8 + (grp & 1) * 8;
                int kk = ks + (grp >> 1) * 8;
                ldmat_x4(af[mi], ab + row * (GST * 2) + kk * 2);
            }
#pragma unroll
            for (int np = 0; np < 4; np++) {
                int n = wc * 64 + np * 16 + r8 + (grp >> 1) * 8;
                int kk = ks + (grp & 1) * 8;
                ldmat_x4(bf[np], bb + n * (GST * 2) + kk * 2);
            }
#pragma unroll
            for (int mi = 0; mi < 4; mi++)
#pragma unroll
                for (int ni = 0; ni < 8; ni++) {
                    uint32_t bq[2] = {bf[ni >> 1][(ni & 1) * 2],
                                      bf[ni >> 1][(ni & 1) * 2 + 1]};
                    mma_f16(acc[mi][ni], af[mi], bq);
                }
        }
        __syncthreads();
    }

    // epilogue
#pragma unroll
    for (int mi = 0; mi < 4; mi++) {
#pragma unroll
        for (int ni = 0; ni < 8; ni++) {
            int r0 = rowBlk + wr * 64 + mi * 16 + g;
            int c = colBlk + wc * 64 + ni * 8 + tg * 2;
            float2 bb2 = *(const float2*)(bias + c);
            float2 o0, o1;
            o0.x = acc[mi][ni][0] + bb2.x;
            o0.y = acc[mi][ni][1] + bb2.y;
            o1.x = acc[mi][ni][2] + bb2.x;
            o1.y = acc[mi][ni][3] + bb2.y;
            if (doRelu) {
                o0.x = fmaxf(o0.x, 0.f); o0.y = fmaxf(o0.y, 0.f);
                o1.x = fmaxf(o1.x, 0.f); o1.y = fmaxf(o1.y, 0.f);
            }
            if (res) {
                float2 r0v = *(const float2*)(res + (size_t)r0 * N + c);
                float2 r1v = *(const float2*)(res + (size_t)(r0 + 8) * N + c);
                o0.x += r0v.x; o0.y += r0v.y;
                o1.x += r1v.x; o1.y += r1v.y;
            }
            if (C) {
                *(float2*)(C + (size_t)r0 * N + c) = o0;
                *(float2*)(C + (size_t)(r0 + 8) * N + c) = o1;
            }
            if (Ch) {
                *(__half2*)(Ch + (size_t)r0 * N + c) = __floats2half2_rn(o0.x, o0.y);
                *(__half2*)(Ch + (size_t)(r0 + 8) * N + c) = __floats2half2_rn(o1.x, o1.y);
            }
        }
    }
}

// ---------------- conversions ------------------------------------------------
__global__ __launch_bounds__(256) void f32_to_f16(const float* __restrict__ in,
                                                  __half* __restrict__ out, int n4) {
    int i = blockIdx.x * 256 + threadIdx.x;
    if (i < n4) {
        float4 v = ((const float4*)in)[i];
        ((__half2*)out)[i * 2]     = __floats2half2_rn(v.x, v.y);
        ((__half2*)out)[i * 2 + 1] = __floats2half2_rn(v.z, v.w);
    }
}

// out[n][k] = half(in[k][n]); in is [R rows(K), C cols(N)]
__global__ __launch_bounds__(256) void transpose_h(const float* __restrict__ in,
                                                   __half* __restrict__ out,
                                                   int R, int Ccols) {
    __shared__ float t[32][33];
    int c = blockIdx.x * 32 + threadIdx.x;
    int r0 = blockIdx.y * 32 + threadIdx.y;
#pragma unroll
    for (int i = 0; i < 32; i += 8)
        t[threadIdx.y + i][threadIdx.x] = in[(size_t)(r0 + i) * Ccols + c];
    __syncthreads();
    int oc = blockIdx.y * 32 + threadIdx.x;
    int orr = blockIdx.x * 32 + threadIdx.y;
#pragma unroll
    for (int i = 0; i < 32; i += 8)
        out[(size_t)(orr + i) * R + oc] = __float2half_rn(t[threadIdx.x][threadIdx.y + i]);
}

__global__ void pack_bias2(const float* __restrict__ b0, const float* __restrict__ b1,
                           float* __restrict__ out) {
    int i = blockIdx.x * 256 + threadIdx.x;
    if (i < DMODEL) { out[i] = b0[i]; out[DMODEL + i] = b1[i]; }
}

// ---------------- mask dtype detection + normalization ---------------------
__global__ void detect_mask_stride(const unsigned char* __restrict__ m, int* stride_out) {
    __shared__ int any;
    if (threadIdx.x == 0) any = 0;
    __syncthreads();
    int a = 0;
    for (int j = threadIdx.x; j < 2048; j += 256) a |= m[j * 4 + 1];
    if (a) atomicOr(&any, 1);
    __syncthreads();
    if (threadIdx.x == 0) *stride_out = any ? 1 : 4;
}

__global__ void mask_prep(const unsigned char* __restrict__ m,
                          const int* __restrict__ stridep,
                          unsigned char* __restrict__ em, int* __restrict__ allpad) {
    int b = blockIdx.x;
    int st = *stridep;
    int ok = 1;
    for (int j = threadIdx.x; j < LSEQ; j += 256) {
        unsigned char v = (m[(size_t)(b * LSEQ + j) * st] != 0) ? 1 : 0;
        em[b * LSEQ + j] = v;
        ok &= (int)v;
    }
    ok = __syncthreads_and(ok);
    if (threadIdx.x == 0) allpad[b] = ok;
}

// ---------------- FP16 tensor-core flash attention --------------------------
// kvstride: row stride of kp/vp (packed KV buffer uses 2048).
#define AST 72
#define ATTH_SMEM (4 * 64 * AST * 2 + 64 * 68 * 4 + 4 * 64 * 4)   // 55296

__global__ __launch_bounds__(256) void attn_h(
    const __half* __restrict__ qp, const __half* __restrict__ kp,
    const __half* __restrict__ vp, const unsigned char* __restrict__ em,
    const int* __restrict__ allpad, __half* __restrict__ out, int kvstride) {
    extern __shared__ char smraw[];
    __half* Qs = (__half*)smraw;
    __half* Ks = Qs + 64 * AST;
    __half* Vs = Ks + 64 * AST;
    __half* Ph = Vs + 64 * AST;
    float* Ps = (float*)(Ph + 64 * AST);
    float* rowm = Ps + 64 * 68;
    float* rowl = rowm + 64;
    float* rowa = rowl + 64;
    float* mk = rowa + 64;
    const uint32_t sb = (uint32_t)__cvta_generic_to_shared(smraw);
    const uint32_t qsb = sb, ksb = sb + 64 * AST * 2,
                   vsb = sb + 2 * 64 * AST * 2, phb = sb + 3 * 64 * AST * 2;

    const int b = blockIdx.z, h = blockIdx.y, q0 = blockIdx.x * 64;
    const int tid = threadIdx.x;
    const int lane = tid & 31, warp = tid >> 5;
    const int g = lane >> 2, tg = lane & 3;
    const int grp = lane >> 3, r8 = lane & 7;
    const int wr = warp & 1, wc = warp >> 1;
    const int ap = allpad[b];
    const size_t qoff = ((size_t)(b * LSEQ + q0) * DMODEL) + h * HDIM;

    for (int t = tid; t < 512; t += 256) {
        int i = t >> 3, ch = t & 7;
        *(uint4*)&Qs[i * AST + ch * 8] =
            *(const uint4*)(qp + qoff + (size_t)i * DMODEL + ch * 8);
    }
    if (tid < 64) { rowm[tid] = -1e30f; rowl[tid] = 0.f; }

    float acc[2][2][4];
#pragma unroll
    for (int mi = 0; mi < 2; mi++)
#pragma unroll
        for (int ni = 0; ni < 2; ni++)
#pragma unroll
            for (int v = 0; v < 4; v++) acc[mi][ni][v] = 0.f;

    for (int kt = 0; kt < 16; kt++) {
        const size_t koff = ((size_t)(b * LSEQ + kt * 64) * kvstride) + h * HDIM;
        for (int t = tid; t < 512; t += 256) {
            int j = t >> 3, ch = t & 7;
            *(uint4*)&Ks[j * AST + ch * 8] =
                *(const uint4*)(kp + koff + (size_t)j * kvstride + ch * 8);
            *(uint4*)&Vs[j * AST + ch * 8] =
                *(const uint4*)(vp + koff + (size_t)j * kvstride + ch * 8);
        }
        if (tid < 64) {
            int kidx = kt * 64 + tid;
            int msk = em[b * LSEQ + kidx];
            if (ap && kidx == LSEQ - 1) msk = 0;
            mk[tid] = msk ? 1.0f : 0.0f;
        }
        __syncthreads();

        // ---- S = Q K^T ----
        float s[2][2][4];
#pragma unroll
        for (int mi = 0; mi < 2; mi++)
#pragma unroll
            for (int ni = 0; ni < 2; ni++)
#pragma unroll
                for (int v = 0; v < 4; v++) s[mi][ni][v] = 0.f;
#pragma unroll
        for (int ks = 0; ks < 64; ks += 16) {
            uint32_t af[2][4], bf[4];
#pragma unroll
            for (int mi = 0; mi < 2; mi++) {
                int row = wr * 32 + mi * 16 + r8 + (grp & 1) * 8;
                ldmat_x4(af[mi], qsb + (row * AST + ks + (grp >> 1) * 8) * 2);
            }
            {
                int n = wc * 16 + r8 + (grp >> 1) * 8;
                ldmat_x4(bf, ksb + (n * AST + ks + (grp & 1) * 8) * 2);
            }
#pragma unroll
            for (int mi = 0; mi < 2; mi++)
#pragma unroll
                for (int ni = 0; ni < 2; ni++) {
                    uint32_t bq[2] = {bf[ni * 2], bf[ni * 2 + 1]};
                    mma_f16(s[mi][ni], af[mi], bq);
                }
        }
#pragma unroll
        for (int mi = 0; mi < 2; mi++) {
            int rr = wr * 32 + mi * 16 + g;
#pragma unroll
            for (int ni = 0; ni < 2; ni++) {
                int cc = wc * 16 + ni * 8 + tg * 2;
                float m0 = mk[cc], m1 = mk[cc + 1];
                Ps[rr * 68 + cc]           = (m0 != 0.f) ? -10000.f : s[mi][ni][0] * ATT_SCALE;
                Ps[rr * 68 + cc + 1]       = (m1 != 0.f) ? -10000.f : s[mi][ni][1] * ATT_SCALE;
                Ps[(rr + 8) * 68 + cc]     = (m0 != 0.f) ? -10000.f : s[mi][ni][2] * ATT_SCALE;
                Ps[(rr + 8) * 68 + cc + 1] = (m1 != 0.f) ? -10000.f : s[mi][ni][3] * ATT_SCALE;
            }
        }
        __syncthreads();

        // ---- online softmax (fp32), write P as half ----
        {
            int row = tid >> 2, sub = tid & 3;
            int base = row * 68 + sub * 16;
            float4 p0 = *(float4*)&Ps[base];
            float4 p1 = *(float4*)&Ps[base + 4];
            float4 p2 = *(float4*)&Ps[base + 8];
            float4 p3 = *(float4*)&Ps[base + 12];
            float tm = fmaxf(fmaxf(fmaxf(p0.x, p0.y), fmaxf(p0.z, p0.w)),
                             fmaxf(fmaxf(p1.x, p1.y), fmaxf(p1.z, p1.w)));
            tm = fmaxf(tm, fmaxf(fmaxf(fmaxf(p2.x, p2.y), fmaxf(p2.z, p2.w)),
                                 fmaxf(fmaxf(p3.x, p3.y), fmaxf(p3.z, p3.w))));
            tm = fmaxf(tm, __shfl_xor_sync(0xffffffffu, tm, 1));
            tm = fmaxf(tm, __shfl_xor_sync(0xffffffffu, tm, 2));
            float m_old = rowm[row];
            float newm = fmaxf(m_old, tm);
            p0.x = __expf(p0.x - newm); p0.y = __expf(p0.y - newm);
            p0.z = __expf(p0.z - newm); p0.w = __expf(p0.w - newm);
            p1.x = __expf(p1.x - newm); p1.y = __expf(p1.y - newm);
            p1.z = __expf(p1.z - newm); p1.w = __expf(p1.w - newm);
            p2.x = __expf(p2.x - newm); p2.y = __expf(p2.y - newm);
            p2.z = __expf(p2.z - newm); p2.w = __expf(p2.w - newm);
            p3.x = __expf(p3.x - newm); p3.y = __expf(p3.y - newm);
            p3.z = __expf(p3.z - newm); p3.w = __expf(p3.w - newm);
            __half2 h0 = __floats2half2_rn(p0.x, p0.y);
            __half2 h1 = __floats2half2_rn(p0.z, p0.w);
            __half2 h2 = __floats2half2_rn(p1.x, p1.y);
            __half2 h3 = __floats2half2_rn(p1.z, p1.w);
            __half2 h4 = __floats2half2_rn(p2.x, p2.y);
            __half2 h5 = __floats2half2_rn(p2.z, p2.w);
            __half2 h6 = __floats2half2_rn(p3.x, p3.y);
            __half2 h7 = __floats2half2_rn(p3.z, p3.w);
            __half2* ph = (__half2*)&Ph[row * AST + sub * 16];
            ph[0] = h0; ph[1] = h1; ph[2] = h2; ph[3] = h3;
            ph[4] = h4; ph[5] = h5; ph[6] = h6; ph[7] = h7;
            float sum = __low2float(h0) + __high2float(h0) + __low2float(h1) + __high2float(h1) +
                        __low2float(h2) + __high2float(h2) + __low2float(h3) + __high2float(h3) +
                        __low2float(h4) + __high2float(h4) + __low2float(h5) + __high2float(h5) +
                        __low2float(h6) + __high2float(h6) + __low2float(h7) + __high2float(h7);
            sum += __shfl_xor_sync(0xffffffffu, sum, 1);
            sum += __shfl_xor_sync(0xffffffffu, sum, 2);
            if (sub == 0) {
                float a = __expf(m_old - newm);
                rowa[row] = a;
                rowl[row] = rowl[row] * a + sum;
                rowm[row] = newm;
            }
        }
        __syncthreads();

        // ---- O = O*alpha + P @ V ----
#pragma unroll
        for (int mi = 0; mi < 2; mi++) {
            int rr = wr * 32 + mi * 16 + g;
            float a0 = rowa[rr], a8 = rowa[rr + 8];
#pragma unroll
            for (int ni = 0; ni < 2; ni++) {
                acc[mi][ni][0] *= a0; acc[mi][ni][1] *= a0;
                acc[mi][ni][2] *= a8; acc[mi][ni][3] *= a8;
            }
        }
#pragma unroll
        for (int ks = 0; ks < 64; ks += 16) {
            uint32_t af[2][4], bf[4];
#pragma unroll
            for (int mi = 0; mi < 2; mi++) {
                int row = wr * 32 + mi * 16 + r8 + (grp & 1) * 8;
                ldmat_x4(af[mi], phb + (row * AST + ks + (grp >> 1) * 8) * 2);
            }
            {
                int j = ks + r8 + (grp & 1) * 8;
                int d = wc * 16 + (grp >> 1) * 8;
                ldmat_x4t(bf, vsb + (j * AST + d) * 2);
            }
#pragma unroll
            for (int mi = 0; mi < 2; mi++)
#pragma unroll
                for (int ni = 0; ni < 2; ni++) {
                    uint32_t bq[2] = {bf[ni * 2], bf[ni * 2 + 1]};
                    mma_f16(acc[mi][ni], af[mi], bq);
                }
        }
        __syncthreads();
    }

#pragma unroll
    for (int mi = 0; mi < 2; mi++) {
        int rr = wr * 32 + mi * 16 + g;
        float i0v = 1.0f / rowl[rr];
        float i8v = 1.0f / rowl[rr + 8];
#pragma unroll
        for (int ni = 0; ni < 2; ni++) {
            int cc = wc * 16 + ni * 8 + tg * 2;
            *(__half2*)(out + ((size_t)(b * LSEQ + q0 + rr) * DMODEL) + h * HDIM + cc) =
                __floats2half2_rn(acc[mi][ni][0] * i0v, acc[mi][ni][1] * i0v);
            *(__half2*)(out + ((size_t)(b * LSEQ + q0 + rr + 8) * DMODEL) + h * HDIM + cc) =
                __floats2half2_rn(acc[mi][ni][2] * i8v, acc[mi][ni][3] * i8v);
        }
    }
}

// ---------------- LayerNorm (optional half twin output) --------------------
__global__ __launch_bounds__(256) void ln_kernel(
    const float* __restrict__ X, const float* __restrict__ gam,
    const float* __restrict__ bet, float* __restrict__ Y, __half* __restrict__ Yh) {
    __shared__ float red[8];
    __shared__ float sMean, sVar;
    const int row = blockIdx.x;
    const int tid = threadIdx.x;
    const float* x = X + (size_t)row * DMODEL;
    float4 v = *(const float4*)(x + tid * 4);
    float s = v.x + v.y + v.z + v.w;
#pragma unroll
    for (int o = 16; o; o >>= 1) s += __shfl_xor_sync(0xffffffffu, s, o);
    int w = tid >> 5, lane = tid & 31;
    if (lane == 0) red[w] = s;
    __syncthreads();
    if (tid == 0) {
        float t = 0;
#pragma unroll
        for (int i = 0; i < 8; i++) t += red[i];
        sMean = t * (1.0f / DMODEL);
    }
    __syncthreads();
    float m = sMean;
    float dx = v.x - m, dy = v.y - m, dz = v.z - m, dw = v.w - m;
    float q = dx * dx + dy * dy + dz * dz + dw * dw;
#pragma unroll
    for (int o = 16; o; o >>= 1) q += __shfl_xor_sync(0xffffffffu, q, o);
    if (lane == 0) red[w] = q;
    __syncthreads();
    if (tid == 0) {
        float t = 0;
#pragma unroll
        for (int i = 0; i < 8; i++) t += red[i];
        sVar = t * (1.0f / DMODEL);
    }
    __syncthreads();
    float inv = rsqrtf(sVar + LN_EPS);
    float4 gv = *(const float4*)(gam + tid * 4);
    float4 bv = *(const float4*)(bet + tid * 4);
    float4 o;
    o.x = dx * inv * gv.x + bv.x;
    o.y = dy * inv * gv.y + bv.y;
    o.z = dz * inv * gv.z + bv.z;
    o.w = dw * inv * gv.w + bv.w;
    *(float4*)(Y + (size_t)row * DMODEL + tid * 4) = o;
    if (Yh) {
        __half2* yh = (__half2*)(Yh + (size_t)row * DMODEL + tid * 4);
        yh[0] = __floats2half2_rn(o.x, o.y);
        yh[1] = __floats2half2_rn(o.z, o.w);
    }
}

// ---------------- launch ----------------------------------------------------
extern "C" void kernel_launch(void* const* d_in, const int* in_sizes, int n_in,
                              void* d_out, int out_size) {
    const float* q  = (const float*)d_in[0];
    const float* kv = (const float*)d_in[1];
    const unsigned char* kvm = (const unsigned char*)d_in[2];
    const float* Wq = (const float*)d_in[3];
    const float* bq = (const float*)d_in[4];
    const float* Wk = (const float*)d_in[5];
    const float* bk = (const float*)d_in[6];
    const float* Wv = (const float*)d_in[7];
    const float* bv = (const float*)d_in[8];
    const float* Wo = (const float*)d_in[9];
    const float* bo = (const float*)d_in[10];
    const float* ln1g = (const float*)d_in[11];
    const float* ln1b = (const float*)d_in[12];
    const float* W1 = (const float*)d_in[13];
    const float* b1 = (const float*)d_in[14];
    const float* W2 = (const float*)d_in[15];
    const float* b2 = (const float*)d_in[16];
    const float* ln2g = (const float*)d_in[17];
    const float* ln2b = (const float*)d_in[18];
    float* out = (float*)d_out;

    __half *qh, *kvh, *qph, *kvph, *atth, *xh, *hh;
    __half *wqt, *wkvt, *wot, *w1t, *w2t;
    float *y, *x, *bkv;
    int *allpad, *mstride;
    unsigned char* emask;
    cudaGetSymbolAddress((void**)&qh, g_qh);
    cudaGetSymbolAddress((void**)&kvh, g_kvh);
    cudaGetSymbolAddress((void**)&qph, g_qph);
    cudaGetSymbolAddress((void**)&kvph, g_kvph);
    cudaGetSymbolAddress((void**)&atth, g_atth);
    cudaGetSymbolAddress((void**)&xh, g_xh);
    cudaGetSymbolAddress((void**)&hh, g_hh);
    cudaGetSymbolAddress((void**)&wqt, g_wqt);
    cudaGetSymbolAddress((void**)&wkvt, g_wkvt);
    cudaGetSymbolAddress((void**)&wot, g_wot);
    cudaGetSymbolAddress((void**)&w1t, g_w1t);
    cudaGetSymbolAddress((void**)&w2t, g_w2t);
    cudaGetSymbolAddress((void**)&bkv, g_bkv);
    cudaGetSymbolAddress((void**)&y, g_y);
    cudaGetSymbolAddress((void**)&x, g_x);
    cudaGetSymbolAddress((void**)&allpad, g_allpad);
    cudaGetSymbolAddress((void**)&emask, g_emask);
    cudaGetSymbolAddress((void**)&mstride, g_mstride);

    cudaFuncSetAttribute(hgemm, cudaFuncAttributeMaxDynamicSharedMemorySize, HG_SMEM);
    cudaFuncSetAttribute(attn_h, cudaFuncAttributeMaxDynamicSharedMemorySize, ATTH_SMEM);

    dim3 blk(256);
    dim3 t32(32, 8);

    // mask normalization
    detect_mask_stride<<<1, 256>>>(kvm, mstride);
    mask_prep<<<BATCH, 256>>>(kvm, mstride, emask, allpad);

    // operand prep
    f32_to_f16<<<(MROWS * DMODEL / 4 + 255) / 256, 256>>>(q,  qh,  MROWS * DMODEL / 4);
    f32_to_f16<<<(MROWS * DMODEL / 4 + 255) / 256, 256>>>(kv, kvh, MROWS * DMODEL / 4);
    transpose_h<<<dim3(32, 32), t32>>>(Wq, wqt, DMODEL, DMODEL);
    transpose_h<<<dim3(32, 32), t32>>>(Wk, wkvt, DMODEL, DMODEL);
    transpose_h<<<dim3(32, 32), t32>>>(Wv, wkvt + DMODEL * DMODEL, DMODEL, DMODEL);
    transpose_h<<<dim3(32, 32), t32>>>(Wo, wot, DMODEL, DMODEL);
    transpose_h<<<dim3(128, 32), t32>>>(W1, w1t, DMODEL, DFF);
    transpose_h<<<dim3(32, 128), t32>>>(W2, w2t, DFF, DMODEL);
    pack_bias2<<<(DMODEL + 255) / 256, 256>>>(bk, bv, bkv);

    // Q projection; fused K+V projection (N=2048, packed output)
    hgemm<<<dim3(4, 64), blk, HG_SMEM>>>(qh, wqt, bq, nullptr, nullptr, qph,
                                         MROWS, DMODEL, DMODEL, 0);
    hgemm<<<dim3(8, 64), blk, HG_SMEM>>>(kvh, wkvt, bkv, nullptr, nullptr, kvph,
                                         MROWS, 2 * DMODEL, DMODEL, 0);

    // attention (kp = packed cols 0..1023, vp = cols 1024..2047)
    attn_h<<<dim3(LSEQ / 64, NHEAD, BATCH), blk, ATTH_SMEM>>>(
        qph, kvph, kvph + DMODEL, emask, allpad, atth, 2 * DMODEL);

    // O projection + residual (fp32 q), LN1
    hgemm<<<dim3(4, 64), blk, HG_SMEM>>>(atth, wot, bo, q, y, nullptr,
                                         MROWS, DMODEL, DMODEL, 0);
    ln_kernel<<<MROWS, blk>>>(y, ln1g, ln1b, x, xh);

    // FFN
    hgemm<<<dim3(16, 64), blk, HG_SMEM>>>(xh, w1t, b1, nullptr, nullptr, hh,
                                          MROWS, DFF, DMODEL, 1);
    hgemm<<<dim3(4, 64), blk, HG_SMEM>>>(hh, w2t, b2, x, y, nullptr,
                                         MROWS, DMODEL, DFF, 0);

    // LN2 -> output
    ln_kernel<<<MROWS, blk>>>(y, ln2g, ln2b, out, nullptr);
}

// round 8
// speedup vs baseline: 6.5847x; 1.1116x over previous
#include <cuda_runtime.h>
#include <cuda_fp16.h>
#include <stdint.h>
#include <math.h>

// Problem constants
#define BATCH 8
#define LSEQ 1024
#define DMODEL 1024
#define NHEAD 16
#define HDIM 64
#define DFF 4096
#define MROWS (BATCH * LSEQ)   // 8192
#define ATT_SCALE 0.125f
#define LN_EPS 1e-5f

// ---------------- scratch (device globals; no allocation allowed) ----------
__device__ __half g_qh[MROWS * DMODEL];
__device__ __half g_kvh[MROWS * DMODEL];
__device__ __half g_qph[MROWS * DMODEL];
__device__ __half g_kvph[(size_t)MROWS * 2 * DMODEL];   // packed [row][K|V]
__device__ __half g_atth[MROWS * DMODEL];
__device__ __half g_xh[MROWS * DMODEL];
__device__ __half g_hh[(size_t)MROWS * DFF];
__device__ __half g_wqt[DMODEL * DMODEL];               // [N][K] half
__device__ __half g_wkvt[2 * DMODEL * DMODEL];          // packed Wk^T|Wv^T
__device__ __half g_wot[DMODEL * DMODEL];
__device__ __half g_w1t[DMODEL * DFF];
__device__ __half g_w2t[DFF * DMODEL];
__device__ float g_bkv[2 * DMODEL];
__device__ float g_y[MROWS * DMODEL];
__device__ float g_x[MROWS * DMODEL];
__device__ int g_allpad[BATCH];
__device__ unsigned char g_emask[BATCH * LSEQ];
__device__ int g_mstride[1];

// ---------------- helpers ----------------------------------------------------
__device__ __forceinline__ void cpa16(uint32_t s, const void* g) {
    asm volatile("cp.async.cg.shared.global [%0], [%1], 16;\n" :: "r"(s), "l"(g));
}
__device__ __forceinline__ void ldmat_x4(uint32_t* r, uint32_t addr) {
    asm volatile("ldmatrix.sync.aligned.m8n8.x4.shared.b16 {%0,%1,%2,%3}, [%4];"
        : "=r"(r[0]), "=r"(r[1]), "=r"(r[2]), "=r"(r[3]) : "r"(addr));
}
__device__ __forceinline__ void ldmat_x4t(uint32_t* r, uint32_t addr) {
    asm volatile("ldmatrix.sync.aligned.m8n8.x4.trans.shared.b16 {%0,%1,%2,%3}, [%4];"
        : "=r"(r[0]), "=r"(r[1]), "=r"(r[2]), "=r"(r[3]) : "r"(addr));
}
__device__ __forceinline__ void mma_f16(float* c, const uint32_t* a, const uint32_t* b) {
    asm volatile(
        "mma.sync.aligned.m16n8k16.row.col.f32.f16.f16.f32 "
        "{%0,%1,%2,%3}, {%4,%5,%6,%7}, {%8,%9}, {%0,%1,%2,%3};"
        : "+f"(c[0]), "+f"(c[1]), "+f"(c[2]), "+f"(c[3])
        : "r"(a[0]), "r"(a[1]), "r"(a[2]), "r"(a[3]), "r"(b[0]), "r"(b[1]));
}

// ---------------- FP16 tensor-core GEMM (128x256 tile, BK=64) ---------------
#define GST 72
#define A_STAGE (128 * GST * 2)
#define B_STAGE (256 * GST * 2)
#define HG_SMEM (2 * (A_STAGE + B_STAGE))  // 110592 B

__device__ __forceinline__ void hfill(const __half* __restrict__ A,
                                      const __half* __restrict__ Bt, int K,
                                      int rowBlk, int colBlk, int kt,
                                      uint32_t abase, uint32_t bbase, int tid) {
#pragma unroll
    for (int c = tid; c < 1024; c += 256) {
        int row = c >> 3, ch = c & 7;
        cpa16(abase + row * (GST * 2) + ch * 16,
              A + (size_t)(rowBlk + row) * K + kt * 64 + ch * 8);
    }
#pragma unroll
    for (int c = tid; c < 2048; c += 256) {
        int row = c >> 3, ch = c & 7;
        cpa16(bbase + row * (GST * 2) + ch * 16,
              Bt + (size_t)(colBlk + row) * K + kt * 64 + ch * 8);
    }
}

__global__ __launch_bounds__(256, 1) void hgemm(
    const __half* __restrict__ A, const __half* __restrict__ Bt,
    const float* __restrict__ bias, const float* __restrict__ res,
    float* __restrict__ C, __half* __restrict__ Ch,
    int M, int N, int K, int doRelu) {
    extern __shared__ char smraw[];
    const uint32_t sb = (uint32_t)__cvta_generic_to_shared(smraw);
    const uint32_t asb = sb;
    const uint32_t bsb = sb + 2 * A_STAGE;

    const int tid = threadIdx.x;
    const int lane = tid & 31, warp = tid >> 5;
    const int wr = warp & 1, wc = warp >> 1;
    const int g = lane >> 2, tg = lane & 3;
    const int grp = lane >> 3, r8 = lane & 7;
    const int rowBlk = blockIdx.y * 128, colBlk = blockIdx.x * 256;

    float acc[4][8][4];
#pragma unroll
    for (int i = 0; i < 4; i++)
#pragma unroll
        for (int j = 0; j < 8; j++)
#pragma unroll
            for (int v = 0; v < 4; v++) acc[i][j][v] = 0.f;

    const int nk = K / 64;

    hfill(A, Bt, K, rowBlk, colBlk, 0, asb, bsb, tid);
    asm volatile("cp.async.commit_group;");

    for (int kt = 0; kt < nk; kt++) {
        if (kt + 1 < nk) {
            int s2 = (kt + 1) & 1;
            hfill(A, Bt, K, rowBlk, colBlk, kt + 1,
                  asb + s2 * A_STAGE, bsb + s2 * B_STAGE, tid);
            asm volatile("cp.async.commit_group;");
            asm volatile("cp.async.wait_group 1;");
        } else {
            asm volatile("cp.async.wait_group 0;");
        }
        __syncthreads();
        const uint32_t ab = asb + (kt & 1) * A_STAGE;
        const uint32_t bb = bsb + (kt & 1) * B_STAGE;
#pragma unroll
        for (int ks = 0; ks < 64; ks += 16) {
            uint32_t af[4][4], bf[4][4];
#pragma unroll
            for (int mi = 0; mi < 4; mi++) {
                int row = wr * 64 + mi * 16 + r8 + (grp & 1) * 8;
                int kk = ks + (grp >> 1) * 8;
                ldmat_x4(af[mi], ab + row * (GST * 2) + kk * 2);
            }
#pragma unroll
            for (int np = 0; np < 4; np++) {
                int n = wc * 64 + np * 16 + r8 + (grp >> 1) * 8;
                int kk = ks + (grp & 1) * 8;
                ldmat_x4(bf[np], bb + n * (GST * 2) + kk * 2);
            }
#pragma unroll
            for (int mi = 0; mi < 4; mi++)
#pragma unroll
                for (int ni = 0; ni < 8; ni++) {
                    uint32_t bq[2] = {bf[ni >> 1][(ni & 1) * 2],
                                      bf[ni >> 1][(ni & 1) * 2 + 1]};
                    mma_f16(acc[mi][ni], af[mi], bq);
                }
        }
        __syncthreads();
    }

#pragma unroll
    for (int mi = 0; mi < 4; mi++) {
#pragma unroll
        for (int ni = 0; ni < 8; ni++) {
            int r0 = rowBlk + wr * 64 + mi * 16 + g;
            int c = colBlk + wc * 64 + ni * 8 + tg * 2;
            float2 bb2 = *(const float2*)(bias + c);
            float2 o0, o1;
            o0.x = acc[mi][ni][0] + bb2.x;
            o0.y = acc[mi][ni][1] + bb2.y;
            o1.x = acc[mi][ni][2] + bb2.x;
            o1.y = acc[mi][ni][3] + bb2.y;
            if (doRelu) {
                o0.x = fmaxf(o0.x, 0.f); o0.y = fmaxf(o0.y, 0.f);
                o1.x = fmaxf(o1.x, 0.f); o1.y = fmaxf(o1.y, 0.f);
            }
            if (res) {
                float2 r0v = *(const float2*)(res + (size_t)r0 * N + c);
                float2 r1v = *(const float2*)(res + (size_t)(r0 + 8) * N + c);
                o0.x += r0v.x; o0.y += r0v.y;
                o1.x += r1v.x; o1.y += r1v.y;
            }
            if (C) {
                *(float2*)(C + (size_t)r0 * N + c) = o0;
                *(float2*)(C + (size_t)(r0 + 8) * N + c) = o1;
            }
            if (Ch) {
                *(__half2*)(Ch + (size_t)r0 * N + c) = __floats2half2_rn(o0.x, o0.y);
                *(__half2*)(Ch + (size_t)(r0 + 8) * N + c) = __floats2half2_rn(o1.x, o1.y);
            }
        }
    }
}

// ---------------- conversions ------------------------------------------------
__global__ __launch_bounds__(256) void f32_to_f16(const float* __restrict__ in,
                                                  __half* __restrict__ out, int n4) {
    int i = blockIdx.x * 256 + threadIdx.x;
    if (i < n4) {
        float4 v = ((const float4*)in)[i];
        ((__half2*)out)[i * 2]     = __floats2half2_rn(v.x, v.y);
        ((__half2*)out)[i * 2 + 1] = __floats2half2_rn(v.z, v.w);
    }
}

__global__ __launch_bounds__(256) void transpose_h(const float* __restrict__ in,
                                                   __half* __restrict__ out,
                                                   int R, int Ccols) {
    __shared__ float t[32][33];
    int c = blockIdx.x * 32 + threadIdx.x;
    int r0 = blockIdx.y * 32 + threadIdx.y;
#pragma unroll
    for (int i = 0; i < 32; i += 8)
        t[threadIdx.y + i][threadIdx.x] = in[(size_t)(r0 + i) * Ccols + c];
    __syncthreads();
    int oc = blockIdx.y * 32 + threadIdx.x;
    int orr = blockIdx.x * 32 + threadIdx.y;
#pragma unroll
    for (int i = 0; i < 32; i += 8)
        out[(size_t)(orr + i) * R + oc] = __float2half_rn(t[threadIdx.x][threadIdx.y + i]);
}

__global__ void pack_bias2(const float* __restrict__ b0, const float* __restrict__ b1,
                           float* __restrict__ out) {
    int i = blockIdx.x * 256 + threadIdx.x;
    if (i < DMODEL) { out[i] = b0[i]; out[DMODEL + i] = b1[i]; }
}

// ---------------- mask dtype detection + normalization ---------------------
__global__ void detect_mask_stride(const unsigned char* __restrict__ m, int* stride_out) {
    __shared__ int any;
    if (threadIdx.x == 0) any = 0;
    __syncthreads();
    int a = 0;
    for (int j = threadIdx.x; j < 2048; j += 256) a |= m[j * 4 + 1];
    if (a) atomicOr(&any, 1);
    __syncthreads();
    if (threadIdx.x == 0) *stride_out = any ? 1 : 4;
}

__global__ void mask_prep(const unsigned char* __restrict__ m,
                          const int* __restrict__ stridep,
                          unsigned char* __restrict__ em, int* __restrict__ allpad) {
    int b = blockIdx.x;
    int st = *stridep;
    int ok = 1;
    for (int j = threadIdx.x; j < LSEQ; j += 256) {
        unsigned char v = (m[(size_t)(b * LSEQ + j) * st] != 0) ? 1 : 0;
        em[b * LSEQ + j] = v;
        ok &= (int)v;
    }
    ok = __syncthreads_and(ok);
    if (threadIdx.x == 0) allpad[b] = ok;
}

// ---------------- FA2-style fp16 flash attention -----------------------------
// Q tile 128 rows; 8 warps, each warp handles 16 rows x all 64 keys.
// Softmax fully in registers (+shfl over quad lanes). No P smem roundtrip:
// S C-frags repack directly into PV A-frags. K/V double-buffered cp.async.
#define AST 72
#define KV_BUF (64 * AST)           // halves per buffer per operand
#define ATT2_SMEM (128 * AST * 2 + 4 * KV_BUF * 2 + 2 * 64 * 4)

__global__ __launch_bounds__(256) void attn_fa(
    const __half* __restrict__ qp, const __half* __restrict__ kp,
    const __half* __restrict__ vp, const unsigned char* __restrict__ em,
    const int* __restrict__ allpad, __half* __restrict__ out, int kvstride) {
    extern __shared__ char smraw[];
    __half* Qs = (__half*)smraw;                 // 128 x AST
    __half* Ks = Qs + 128 * AST;                 // 2 x KV_BUF
    __half* Vs = Ks + 2 * KV_BUF;                // 2 x KV_BUF
    float* mk = (float*)(Vs + 2 * KV_BUF);       // 2 x 64
    const uint32_t sb = (uint32_t)__cvta_generic_to_shared(smraw);
    const uint32_t qsb = sb;
    const uint32_t ksb = sb + 128 * AST * 2;
    const uint32_t vsb = ksb + 2 * KV_BUF * 2;

    const int b = blockIdx.z, h = blockIdx.y, q0 = blockIdx.x * 128;
    const int tid = threadIdx.x;
    const int lane = tid & 31, warp = tid >> 5;
    const int g = lane >> 2, tg = lane & 3;
    const int grp = lane >> 3, r8 = lane & 7;
    const int ap = allpad[b];
    const size_t qoff = ((size_t)(b * LSEQ + q0) * DMODEL) + h * HDIM;

    // prologue: stage K/V tile 0
    {
        const size_t koff = ((size_t)(b * LSEQ) * kvstride) + h * HDIM;
        for (int t = tid; t < 512; t += 256) {
            int row = t >> 3, ch = t & 7;
            cpa16(ksb + row * (AST * 2) + ch * 16, kp + koff + (size_t)row * kvstride + ch * 8);
            cpa16(vsb + row * (AST * 2) + ch * 16, vp + koff + (size_t)row * kvstride + ch * 8);
        }
        asm volatile("cp.async.commit_group;");
    }
    // stage Q
    for (int t = tid; t < 1024; t += 256) {
        int i = t >> 3, ch = t & 7;
        *(uint4*)&Qs[i * AST + ch * 8] =
            *(const uint4*)(qp + qoff + (size_t)i * DMODEL + ch * 8);
    }
    // mask for tile 0
    if (tid < 64) {
        int msk = em[b * LSEQ + tid];
        mk[tid] = msk ? 1.0f : 0.0f;
    }
    __syncthreads();

    // Q fragments (persist across all key tiles)
    uint32_t qf[4][4];
#pragma unroll
    for (int c = 0; c < 4; c++) {
        int row = 16 * warp + r8 + (grp & 1) * 8;
        int kk = 16 * c + (grp >> 1) * 8;
        ldmat_x4(qf[c], qsb + (row * AST + kk) * 2);
    }

    float m0 = -1e30f, m1 = -1e30f, l0 = 0.f, l1 = 0.f;
    float acc[8][4];
#pragma unroll
    for (int i = 0; i < 8; i++)
#pragma unroll
        for (int v = 0; v < 4; v++) acc[i][v] = 0.f;

    for (int kt = 0; kt < 16; kt++) {
        const int cur = kt & 1;
        if (kt + 1 < 16) {
            const int nxt = (kt + 1) & 1;
            const size_t koff = ((size_t)(b * LSEQ + (kt + 1) * 64) * kvstride) + h * HDIM;
            for (int t = tid; t < 512; t += 256) {
                int row = t >> 3, ch = t & 7;
                cpa16(ksb + nxt * KV_BUF * 2 + row * (AST * 2) + ch * 16,
                      kp + koff + (size_t)row * kvstride + ch * 8);
                cpa16(vsb + nxt * KV_BUF * 2 + row * (AST * 2) + ch * 16,
                      vp + koff + (size_t)row * kvstride + ch * 8);
            }
            asm volatile("cp.async.commit_group;");
            asm volatile("cp.async.wait_group 1;");
        } else {
            asm volatile("cp.async.wait_group 0;");
        }
        __syncthreads();
        // mask for next tile (written after barrier; consumed after next barrier)
        if (kt + 1 < 16 && tid < 64) {
            int kidx = (kt + 1) * 64 + tid;
            int msk = em[b * LSEQ + kidx];
            if (ap && kidx == LSEQ - 1) msk = 0;
            mk[((kt + 1) & 1) * 64 + tid] = msk ? 1.0f : 0.0f;
        }

        const uint32_t kb = ksb + cur * KV_BUF * 2;
        const uint32_t vb = vsb + cur * KV_BUF * 2;
        const float* mkc = mk + cur * 64;

        // ---- S = Q K^T : warp covers 16 rows x 64 keys ----
        float s[8][4];
#pragma unroll
        for (int i = 0; i < 8; i++)
#pragma unroll
            for (int v = 0; v < 4; v++) s[i][v] = 0.f;
#pragma unroll
        for (int c = 0; c < 4; c++) {
#pragma unroll
            for (int ng = 0; ng < 4; ng++) {
                uint32_t bf[4];
                int n = 16 * ng + r8 + (grp >> 1) * 8;
                int kk = 16 * c + (grp & 1) * 8;
                ldmat_x4(bf, kb + (n * AST + kk) * 2);
                uint32_t b0[2] = {bf[0], bf[1]};
                uint32_t b1[2] = {bf[2], bf[3]};
                mma_f16(s[2 * ng], qf[c], b0);
                mma_f16(s[2 * ng + 1], qf[c], b1);
            }
        }

        // ---- scale + mask ----
#pragma unroll
        for (int ni = 0; ni < 8; ni++) {
            int c0 = ni * 8 + tg * 2;
            float k0 = mkc[c0], k1 = mkc[c0 + 1];
            s[ni][0] = (k0 != 0.f) ? -10000.f : s[ni][0] * ATT_SCALE;
            s[ni][1] = (k1 != 0.f) ? -10000.f : s[ni][1] * ATT_SCALE;
            s[ni][2] = (k0 != 0.f) ? -10000.f : s[ni][2] * ATT_SCALE;
            s[ni][3] = (k1 != 0.f) ? -10000.f : s[ni][3] * ATT_SCALE;
        }

        // ---- register softmax (reduce over quad tg lanes) ----
        float mt0 = -1e30f, mt1 = -1e30f;
#pragma unroll
        for (int ni = 0; ni < 8; ni++) {
            mt0 = fmaxf(mt0, fmaxf(s[ni][0], s[ni][1]));
            mt1 = fmaxf(mt1, fmaxf(s[ni][2], s[ni][3]));
        }
        mt0 = fmaxf(mt0, __shfl_xor_sync(0xffffffffu, mt0, 1));
        mt0 = fmaxf(mt0, __shfl_xor_sync(0xffffffffu, mt0, 2));
        mt1 = fmaxf(mt1, __shfl_xor_sync(0xffffffffu, mt1, 1));
        mt1 = fmaxf(mt1, __shfl_xor_sync(0xffffffffu, mt1, 2));
        float nm0 = fmaxf(m0, mt0), nm1 = fmaxf(m1, mt1);
        float a0 = __expf(m0 - nm0), a1 = __expf(m1 - nm1);

        uint32_t pa[8], pb[8];
        float sum0 = 0.f, sum1 = 0.f;
#pragma unroll
        for (int ni = 0; ni < 8; ni++) {
            __half2 hA = __floats2half2_rn(__expf(s[ni][0] - nm0), __expf(s[ni][1] - nm0));
            __half2 hB = __floats2half2_rn(__expf(s[ni][2] - nm1), __expf(s[ni][3] - nm1));
            pa[ni] = *(uint32_t*)&hA;
            pb[ni] = *(uint32_t*)&hB;
            sum0 += __low2float(hA) + __high2float(hA);
            sum1 += __low2float(hB) + __high2float(hB);
        }
        sum0 += __shfl_xor_sync(0xffffffffu, sum0, 1);
        sum0 += __shfl_xor_sync(0xffffffffu, sum0, 2);
        sum1 += __shfl_xor_sync(0xffffffffu, sum1, 1);
        sum1 += __shfl_xor_sync(0xffffffffu, sum1, 2);
        m0 = nm0; m1 = nm1;
        l0 = l0 * a0 + sum0;
        l1 = l1 * a1 + sum1;
#pragma unroll
        for (int ni = 0; ni < 8; ni++) {
            acc[ni][0] *= a0; acc[ni][1] *= a0;
            acc[ni][2] *= a1; acc[ni][3] *= a1;
        }

        // ---- O += P @ V (P repacked from S C-frags in registers) ----
#pragma unroll
        for (int c = 0; c < 4; c++) {
            uint32_t af[4] = {pa[2 * c], pb[2 * c], pa[2 * c + 1], pb[2 * c + 1]};
#pragma unroll
            for (int dg = 0; dg < 4; dg++) {
                uint32_t bf[4];
                int j = 16 * c + r8 + (grp & 1) * 8;
                int d = 16 * dg + (grp >> 1) * 8;
                ldmat_x4t(bf, vb + (j * AST + d) * 2);
                uint32_t b0[2] = {bf[0], bf[1]};
                uint32_t b1[2] = {bf[2], bf[3]};
                mma_f16(acc[2 * dg], af, b0);
                mma_f16(acc[2 * dg + 1], af, b1);
            }
        }
        __syncthreads();   // all reads of buf[cur] done before its refill next iter
    }

    // ---- normalize + write (half) ----
    float i0v = 1.0f / l0, i1v = 1.0f / l1;
    int r0 = q0 + 16 * warp + g;
#pragma unroll
    for (int ni = 0; ni < 8; ni++) {
        int cc = h * HDIM + ni * 8 + tg * 2;
        *(__half2*)(out + (size_t)(b * LSEQ + r0) * DMODEL + cc) =
            __floats2half2_rn(acc[ni][0] * i0v, acc[ni][1] * i0v);
        *(__half2*)(out + (size_t)(b * LSEQ + r0 + 8) * DMODEL + cc) =
            __floats2half2_rn(acc[ni][2] * i1v, acc[ni][3] * i1v);
    }
}

// ---------------- LayerNorm (optional half twin output) --------------------
__global__ __launch_bounds__(256) void ln_kernel(
    const float* __restrict__ X, const float* __restrict__ gam,
    const float* __restrict__ bet, float* __restrict__ Y, __half* __restrict__ Yh) {
    __shared__ float red[8];
    __shared__ float sMean, sVar;
    const int row = blockIdx.x;
    const int tid = threadIdx.x;
    const float* x = X + (size_t)row * DMODEL;
    float4 v = *(const float4*)(x + tid * 4);
    float s = v.x + v.y + v.z + v.w;
#pragma unroll
    for (int o = 16; o; o >>= 1) s += __shfl_xor_sync(0xffffffffu, s, o);
    int w = tid >> 5, lane = tid & 31;
    if (lane == 0) red[w] = s;
    __syncthreads();
    if (tid == 0) {
        float t = 0;
#pragma unroll
        for (int i = 0; i < 8; i++) t += red[i];
        sMean = t * (1.0f / DMODEL);
    }
    __syncthreads();
    float m = sMean;
    float dx = v.x - m, dy = v.y - m, dz = v.z - m, dw = v.w - m;
    float q = dx * dx + dy * dy + dz * dz + dw * dw;
#pragma unroll
    for (int o = 16; o; o >>= 1) q += __shfl_xor_sync(0xffffffffu, q, o);
    if (lane == 0) red[w] = q;
    __syncthreads();
    if (tid == 0) {
        float t = 0;
#pragma unroll
        for (int i = 0; i < 8; i++) t += red[i];
        sVar = t * (1.0f / DMODEL);
    }
    __syncthreads();
    float inv = rsqrtf(sVar + LN_EPS);
    float4 gv = *(const float4*)(gam + tid * 4);
    float4 bv = *(const float4*)(bet + tid * 4);
    float4 o;
    o.x = dx * inv * gv.x + bv.x;
    o.y = dy * inv * gv.y + bv.y;
    o.z = dz * inv * gv.z + bv.z;
    o.w = dw * inv * gv.w + bv.w;
    *(float4*)(Y + (size_t)row * DMODEL + tid * 4) = o;
    if (Yh) {
        __half2* yh = (__half2*)(Yh + (size_t)row * DMODEL + tid * 4);
        yh[0] = __floats2half2_rn(o.x, o.y);
        yh[1] = __floats2half2_rn(o.z, o.w);
    }
}

// ---------------- launch ----------------------------------------------------
extern "C" void kernel_launch(void* const* d_in, const int* in_sizes, int n_in,
                              void* d_out, int out_size) {
    const float* q  = (const float*)d_in[0];
    const float* kv = (const float*)d_in[1];
    const unsigned char* kvm = (const unsigned char*)d_in[2];
    const float* Wq = (const float*)d_in[3];
    const float* bq = (const float*)d_in[4];
    const float* Wk = (const float*)d_in[5];
    const float* bk = (const float*)d_in[6];
    const float* Wv = (const float*)d_in[7];
    const float* bv = (const float*)d_in[8];
    const float* Wo = (const float*)d_in[9];
    const float* bo = (const float*)d_in[10];
    const float* ln1g = (const float*)d_in[11];
    const float* ln1b = (const float*)d_in[12];
    const float* W1 = (const float*)d_in[13];
    const float* b1 = (const float*)d_in[14];
    const float* W2 = (const float*)d_in[15];
    const float* b2 = (const float*)d_in[16];
    const float* ln2g = (const float*)d_in[17];
    const float* ln2b = (const float*)d_in[18];
    float* out = (float*)d_out;

    __half *qh, *kvh, *qph, *kvph, *atth, *xh, *hh;
    __half *wqt, *wkvt, *wot, *w1t, *w2t;
    float *y, *x, *bkv;
    int *allpad, *mstride;
    unsigned char* emask;
    cudaGetSymbolAddress((void**)&qh, g_qh);
    cudaGetSymbolAddress((void**)&kvh, g_kvh);
    cudaGetSymbolAddress((void**)&qph, g_qph);
    cudaGetSymbolAddress((void**)&kvph, g_kvph);
    cudaGetSymbolAddress((void**)&atth, g_atth);
    cudaGetSymbolAddress((void**)&xh, g_xh);
    cudaGetSymbolAddress((void**)&hh, g_hh);
    cudaGetSymbolAddress((void**)&wqt, g_wqt);
    cudaGetSymbolAddress((void**)&wkvt, g_wkvt);
    cudaGetSymbolAddress((void**)&wot, g_wot);
    cudaGetSymbolAddress((void**)&w1t, g_w1t);
    cudaGetSymbolAddress((void**)&w2t, g_w2t);
    cudaGetSymbolAddress((void**)&bkv, g_bkv);
    cudaGetSymbolAddress((void**)&y, g_y);
    cudaGetSymbolAddress((void**)&x, g_x);
    cudaGetSymbolAddress((void**)&allpad, g_allpad);
    cudaGetSymbolAddress((void**)&emask, g_emask);
    cudaGetSymbolAddress((void**)&mstride, g_mstride);

    cudaFuncSetAttribute(hgemm, cudaFuncAttributeMaxDynamicSharedMemorySize, HG_SMEM);
    cudaFuncSetAttribute(attn_fa, cudaFuncAttributeMaxDynamicSharedMemorySize, ATT2_SMEM);

    dim3 blk(256);
    dim3 t32(32, 8);

    // launches 0-4: prep (keeps hgemm at ncu -s 5 window)
    detect_mask_stride<<<1, 256>>>(kvm, mstride);                                   // 0
    mask_prep<<<BATCH, 256>>>(kvm, mstride, emask, allpad);                         // 1
    f32_to_f16<<<(MROWS * DMODEL / 4 + 255) / 256, 256>>>(q,  qh,  MROWS * DMODEL / 4);  // 2
    f32_to_f16<<<(MROWS * DMODEL / 4 + 255) / 256, 256>>>(kv, kvh, MROWS * DMODEL / 4);  // 3
    transpose_h<<<dim3(32, 32), t32>>>(Wq, wqt, DMODEL, DMODEL);                    // 4

    // 5: Q projection (profiled by ncu -s 5 -c 1)
    hgemm<<<dim3(4, 64), blk, HG_SMEM>>>(qh, wqt, bq, nullptr, nullptr, qph,
                                         MROWS, DMODEL, DMODEL, 0);                 // 5

    transpose_h<<<dim3(32, 32), t32>>>(Wk, wkvt, DMODEL, DMODEL);                   // 6
    transpose_h<<<dim3(32, 32), t32>>>(Wv, wkvt + DMODEL * DMODEL, DMODEL, DMODEL); // 7
    pack_bias2<<<(DMODEL + 255) / 256, 256>>>(bk, bv, bkv);                         // 8
    hgemm<<<dim3(8, 64), blk, HG_SMEM>>>(kvh, wkvt, bkv, nullptr, nullptr, kvph,
                                         MROWS, 2 * DMODEL, DMODEL, 0);             // 9
    transpose_h<<<dim3(32, 32), t32>>>(Wo, wot, DMODEL, DMODEL);                    // 10
    transpose_h<<<dim3(128, 32), t32>>>(W1, w1t, DMODEL, DFF);                      // 11
    transpose_h<<<dim3(32, 128), t32>>>(W2, w2t, DFF, DMODEL);                      // 12

    // attention (FA2-style)
    attn_fa<<<dim3(LSEQ / 128, NHEAD, BATCH), blk, ATT2_SMEM>>>(
        qph, kvph, kvph + DMODEL, emask, allpad, atth, 2 * DMODEL);                 // 13

    // O projection + residual (fp32 q), LN1
    hgemm<<<dim3(4, 64), blk, HG_SMEM>>>(atth, wot, bo, q, y, nullptr,
                                         MROWS, DMODEL, DMODEL, 0);                 // 14
    ln_kernel<<<MROWS, blk>>>(y, ln1g, ln1b, x, xh);                                // 15

    // FFN
    hgemm<<<dim3(16, 64), blk, HG_SMEM>>>(xh, w1t, b1, nullptr, nullptr, hh,
                                          MROWS, DFF, DMODEL, 1);                   // 16
    hgemm<<<dim3(4, 64), blk, HG_SMEM>>>(hh, w2t, b2, x, y, nullptr,
                                         MROWS, DMODEL, DFF, 0);                    // 17

    // LN2 -> output
    ln_kernel<<<MROWS, blk>>>(y, ln2g, ln2b, out, nullptr);                         // 18
}